// round 4
// baseline (speedup 1.0000x reference)
#include <cuda_runtime.h>
#include <math.h>
#include <stdint.h>

// B=128, T=256, W=256, D=128, C=256, K=12, Tp=244, TEMP=0.1
#define N_BT     32768
#define TP       244
#define NROWS_L  374784
// logits smem: Ut 128x68 + Zt 128x132 floats
#define LOG_SMEM ((128*68 + 128*132)*4)
// GRU smem
#define GRU_SMEM ((96*260 + 4096 + 864 + 1600 + 96)*4)

// ---------------- packed f32x2 helpers ----------------------------------
#define FMA2(d,a,b) asm("fma.rn.f32x2 %0, %1, %2, %0;" : "+l"(d) : "l"(a), "l"(b))
__device__ __forceinline__ unsigned long long pack2(float x) {
    unsigned long long r; asm("mov.b64 %0, {%1, %1};" : "=l"(r) : "f"(x)); return r;
}
__device__ __forceinline__ void unpack2(unsigned long long v, float& lo, float& hi) {
    asm("mov.b64 {%0, %1}, %2;" : "=f"(lo), "=f"(hi) : "l"(v));
}
__device__ __forceinline__ float pairsum(unsigned long long v) {
    float a, b; unpack2(v, a, b); return a + b;
}
__device__ __forceinline__ uint32_t s2u(const void* p) {
    uint32_t a; asm("{ .reg .u64 t; cvta.to.shared.u64 t, %1; cvt.u32.u64 %0, t; }" : "=r"(a) : "l"(p));
    return a;
}
__device__ __forceinline__ uint32_t mapa_u32(uint32_t addr, uint32_t rank) {
    uint32_t r; asm("mapa.shared::cluster.u32 %0, %1, %2;" : "=r"(r) : "r"(addr), "r"(rank));
    return r;
}
__device__ __forceinline__ void st_cluster_f32(uint32_t addr, float v) {
    asm volatile("st.shared::cluster.f32 [%0], %1;" :: "r"(addr), "f"(v) : "memory");
}

// ---------------- scratch ------------------------------------------------
__device__ __align__(16) float g_z   [4194304];   // [32768,128] normalized z
__device__ __align__(16) float g_c   [8388608];   // [32768,256] c_seq
__device__ __align__(16) float g_h1  [8388608];   // [32768,256]
__device__ __align__(16) float g_gx  [25165824];  // [32768,768]
__device__ __align__(16) float g_U   [50331648];  // [12,32768,128] rows scaled by 10/||.||
__device__ __align__(16) float g_w1T [65536];
__device__ __align__(16) float g_w2T [32768];
__device__ __align__(16) float g_WkT [393216];
__device__ __align__(16) float g_part[12288];

// ---------------- prep: transposes --------------------------------------
__global__ void prep_transpose(const float* __restrict__ w1, const float* __restrict__ w2,
                               const float* __restrict__ wk)
{
    long i = (long)blockIdx.x * 256 + threadIdx.x;
    if (i < 65536) {
        int n = (int)(i >> 8), k = (int)(i & 255);
        g_w1T[n*256 + k] = w1[k*256 + n];
    }
    if (i < 32768) {
        int n = (int)(i >> 8), k = (int)(i & 255);
        g_w2T[n*256 + k] = w2[k*128 + n];
    }
    if (i < 393216) {
        long kk = i / 32768; long r = i % 32768;
        int d = (int)(r >> 8), c = (int)(r & 255);
        g_WkT[kk*32768 + d*256 + c] = wk[kk*32768 + c*128 + d];
    }
}

// ---------------- NT GEMM, f32x2, double-buffered, 2 CTAs/SM -------------
// C = A @ B^T + bias. mode: 0 plain(+relu opt), 1 rows *= 10/max(||r||,eps),
// 2 rows *= 1/max(||r||,eps). modes 1/2 require N==128 (gridDim.x==1).
__global__ __launch_bounds__(256, 2) void gemm_nt(
    const float* __restrict__ A, const float* __restrict__ Bm,
    const float* __restrict__ bias, float* __restrict__ Cm,
    int M, int N, int K, int relu, int mode,
    long sB, long sBias, long sC)
{
    __shared__ float AsBs[2][2][16][132];     // [buf][A/B][k][row]
    // epilogue overlay (used after main loop, behind a __syncthreads)
    float (*rs)[17] = (float(*)[17])&AsBs[0][0][0][0];
    float* rinv     = &AsBs[0][0][0][0] + 128*17;

    const float* Bz = Bm  + (long)blockIdx.z * sB;
    const float* bz = bias + (long)blockIdx.z * sBias;
    float*       Cz = Cm  + (long)blockIdx.z * sC;

    int m0 = blockIdx.y * 128, n0 = blockIdx.x * 128;
    int tid = threadIdx.x;
    int tx = tid & 15, ty = tid >> 4;

    const float* Ab = A  + (long)m0 * K;
    const float* Bb = Bz + (long)n0 * K;
    int lrow = tid >> 2, lc4 = (tid & 3) << 2;

    unsigned long long acc2[8][4];
    #pragma unroll
    for (int i = 0; i < 8; i++)
        #pragma unroll
        for (int j = 0; j < 4; j++) acc2[i][j] = 0ULL;

    float4 ra0, ra1, rb0, rb1;
    ra0 = *(const float4*)(Ab + (long)lrow*K + lc4);
    ra1 = *(const float4*)(Ab + (long)(lrow+64)*K + lc4);
    rb0 = *(const float4*)(Bb + (long)lrow*K + lc4);
    rb1 = *(const float4*)(Bb + (long)(lrow+64)*K + lc4);
    {
        float (*As)[132] = AsBs[0][0];
        float (*Bs)[132] = AsBs[0][1];
        As[lc4+0][lrow] = ra0.x; As[lc4+1][lrow] = ra0.y;
        As[lc4+2][lrow] = ra0.z; As[lc4+3][lrow] = ra0.w;
        As[lc4+0][lrow+64] = ra1.x; As[lc4+1][lrow+64] = ra1.y;
        As[lc4+2][lrow+64] = ra1.z; As[lc4+3][lrow+64] = ra1.w;
        Bs[lc4+0][lrow] = rb0.x; Bs[lc4+1][lrow] = rb0.y;
        Bs[lc4+2][lrow] = rb0.z; Bs[lc4+3][lrow] = rb0.w;
        Bs[lc4+0][lrow+64] = rb1.x; Bs[lc4+1][lrow+64] = rb1.y;
        Bs[lc4+2][lrow+64] = rb1.z; Bs[lc4+3][lrow+64] = rb1.w;
    }
    __syncthreads();

    int NT = K >> 4;
    for (int t = 0; t < NT; t++) {
        int cur = t & 1;
        bool nxt = (t + 1 < NT);
        if (nxt) {
            int k0 = (t+1) << 4;
            ra0 = *(const float4*)(Ab + (long)lrow*K + k0 + lc4);
            ra1 = *(const float4*)(Ab + (long)(lrow+64)*K + k0 + lc4);
            rb0 = *(const float4*)(Bb + (long)lrow*K + k0 + lc4);
            rb1 = *(const float4*)(Bb + (long)(lrow+64)*K + k0 + lc4);
        }
        float (*As)[132] = AsBs[cur][0];
        float (*Bs)[132] = AsBs[cur][1];
        #pragma unroll
        for (int kk = 0; kk < 16; kk++) {
            float4 a0 = *(const float4*)&As[kk][ty*8];
            float4 a1 = *(const float4*)&As[kk][ty*8 + 4];
            ulonglong2 b01 = *(const ulonglong2*)&Bs[kk][tx*8];
            ulonglong2 b23 = *(const ulonglong2*)&Bs[kk][tx*8 + 4];
            float a[8] = {a0.x,a0.y,a0.z,a0.w,a1.x,a1.y,a1.z,a1.w};
            #pragma unroll
            for (int i = 0; i < 8; i++) {
                unsigned long long av = pack2(a[i]);
                FMA2(acc2[i][0], av, b01.x);
                FMA2(acc2[i][1], av, b01.y);
                FMA2(acc2[i][2], av, b23.x);
                FMA2(acc2[i][3], av, b23.y);
            }
        }
        if (nxt) {
            int nb = cur ^ 1;
            __syncthreads();
            float (*An)[132] = AsBs[nb][0];
            float (*Bn)[132] = AsBs[nb][1];
            An[lc4+0][lrow] = ra0.x; An[lc4+1][lrow] = ra0.y;
            An[lc4+2][lrow] = ra0.z; An[lc4+3][lrow] = ra0.w;
            An[lc4+0][lrow+64] = ra1.x; An[lc4+1][lrow+64] = ra1.y;
            An[lc4+2][lrow+64] = ra1.z; An[lc4+3][lrow+64] = ra1.w;
            Bn[lc4+0][lrow] = rb0.x; Bn[lc4+1][lrow] = rb0.y;
            Bn[lc4+2][lrow] = rb0.z; Bn[lc4+3][lrow] = rb0.w;
            Bn[lc4+0][lrow+64] = rb1.x; Bn[lc4+1][lrow+64] = rb1.y;
            Bn[lc4+2][lrow+64] = rb1.z; Bn[lc4+3][lrow+64] = rb1.w;
            __syncthreads();
        }
    }

    // epilogue
    float v[8][8];
    float bb[8];
    #pragma unroll
    for (int j = 0; j < 8; j++) bb[j] = bz[n0 + tx*8 + j];
    #pragma unroll
    for (int i = 0; i < 8; i++)
        #pragma unroll
        for (int jp = 0; jp < 4; jp++) {
            float lo, hi; unpack2(acc2[i][jp], lo, hi);
            v[i][2*jp]   = lo + bb[2*jp];
            v[i][2*jp+1] = hi + bb[2*jp+1];
        }

    if (mode) {
        __syncthreads();   // done reading AsBs; safe to overlay
        #pragma unroll
        for (int i = 0; i < 8; i++) {
            float ss = 0.f;
            #pragma unroll
            for (int j = 0; j < 8; j++) ss += v[i][j]*v[i][j];
            rs[ty*8+i][tx] = ss;
        }
        __syncthreads();
        if (tid < 128) {
            float ss = 0.f;
            #pragma unroll
            for (int x = 0; x < 16; x++) ss += rs[tid][x];
            float inv = 1.f / fmaxf(sqrtf(ss), 1e-12f);
            if (mode == 1) inv *= 10.f;
            rinv[tid] = inv;
        }
        __syncthreads();
        #pragma unroll
        for (int i = 0; i < 8; i++) {
            float sc = rinv[ty*8+i];
            #pragma unroll
            for (int j = 0; j < 8; j++) v[i][j] *= sc;
        }
    }

    #pragma unroll
    for (int i = 0; i < 8; i++) {
        float* Crow = Cz + (long)(m0 + ty*8 + i)*N + n0 + tx*8;
        #pragma unroll
        for (int j = 0; j < 8; j++) {
            float x = v[i][j];
            if (relu) x = fmaxf(x, 0.f);
            Crow[j] = x;
        }
    }
}

// ---------------- GRU: weight-stationary 8-CTA clusters ------------------
__global__ __launch_bounds__(256, 1) __cluster_dims__(8, 1, 1)
void gru_cluster(const float* __restrict__ Whh, const float* __restrict__ bhh)
{
    extern __shared__ float s[];
    float* W_s  = s;                       // [96][260]
    float* hb   = s + 96*260;              // [2][8][256]
    float* gh_s = hb + 4096;               // [96][9]
    float* gx_s = gh_s + 864;              // [2][8][100]
    float* bh_s = gx_s + 1600;             // [96]

    int tid  = threadIdx.x;
    int rank = blockIdx.x & 7;
    int cl   = blockIdx.x >> 3;
    int co   = rank * 32;
    int b0   = cl * 8;

    for (int i = tid; i < 96*256; i += 256) {
        int r = i >> 8, k = i & 255;
        int grow = (r >> 5)*256 + co + (r & 31);
        W_s[r*260 + k] = Whh[grow*256 + k];
    }
    if (tid < 96) {
        int grow = (tid >> 5)*256 + co + (tid & 31);
        bh_s[tid] = bhh[grow];
    }
    for (int i = tid; i < 2048; i += 256) hb[i] = 0.f;

    if (tid >= 192) {
        int f = tid - 192;
        for (int i = f; i < 768; i += 64) {
            int b = i / 96, pos = i - b*96;
            gx_s[b*100 + pos] =
                g_gx[((long)(b0+b)*256 + 0)*768 + (pos>>5)*256 + co + (pos&31)];
        }
    }

    int ub = tid >> 5, uc = tid & 31;
    uint32_t local_addr = s2u(hb) + (uint32_t)((ub*256 + co + uc) * 4);
    uint32_t radr[8];
    #pragma unroll
    for (int r = 0; r < 8; r++) radr[r] = mapa_u32(local_addr, r);
    float h_old = 0.f;
    float* cptr = g_c + ((long)(b0+ub)*256)*256 + co + uc;

    int g = tid >> 1, bbase = (tid & 1) * 4;
    __syncthreads();

    for (int t = 0; t < 256; t++) {
        int p = t & 1, pn = p ^ 1;
        const float* hcur = hb + p*2048;

        if (tid < 192) {
            const float* wr = W_s + g*260;
            const float* h0 = hcur + (bbase+0)*256;
            const float* h1 = hcur + (bbase+1)*256;
            const float* h2 = hcur + (bbase+2)*256;
            const float* h3 = hcur + (bbase+3)*256;
            unsigned long long a0=0ULL, a1=0ULL, a2=0ULL, a3=0ULL;
            #pragma unroll 4
            for (int k = 0; k < 64; k++) {
                ulonglong2 w = *(const ulonglong2*)(wr + k*4);
                ulonglong2 x;
                x = *(const ulonglong2*)(h0 + k*4); FMA2(a0, w.x, x.x); FMA2(a0, w.y, x.y);
                x = *(const ulonglong2*)(h1 + k*4); FMA2(a1, w.x, x.x); FMA2(a1, w.y, x.y);
                x = *(const ulonglong2*)(h2 + k*4); FMA2(a2, w.x, x.x); FMA2(a2, w.y, x.y);
                x = *(const ulonglong2*)(h3 + k*4); FMA2(a3, w.x, x.x); FMA2(a3, w.y, x.y);
            }
            gh_s[g*9 + bbase+0] = pairsum(a0);
            gh_s[g*9 + bbase+1] = pairsum(a1);
            gh_s[g*9 + bbase+2] = pairsum(a2);
            gh_s[g*9 + bbase+3] = pairsum(a3);
        } else if (t < 255) {
            int f = tid - 192;
            float* dst = gx_s + pn*800;
            for (int i = f; i < 768; i += 64) {
                int b = i / 96, pos = i - b*96;
                dst[b*100 + pos] =
                    g_gx[((long)(b0+b)*256 + (t+1))*768 + (pos>>5)*256 + co + (pos&31)];
            }
        }
        __syncthreads();

        {
            const float* gxb = gx_s + p*800 + ub*100;
            float xr = gxb[uc], xz = gxb[32+uc], xn = gxb[64+uc];
            float hr = gh_s[uc*9 + ub]        + bh_s[uc];
            float hz = gh_s[(32+uc)*9 + ub]   + bh_s[32+uc];
            float hn = gh_s[(64+uc)*9 + ub]   + bh_s[64+uc];
            float rg = 1.f / (1.f + expf(-(xr + hr)));
            float zg = 1.f / (1.f + expf(-(xz + hz)));
            float ng = tanhf(xn + rg*hn);
            float hnew = (1.f - zg)*ng + zg*h_old;
            h_old = hnew;
            uint32_t off = (uint32_t)(pn * 8192);
            #pragma unroll
            for (int r = 0; r < 8; r++) st_cluster_f32(radr[r] + off, hnew);
            cptr[t*256] = hnew;
        }
        asm volatile("barrier.cluster.arrive.aligned;" ::: "memory");
        asm volatile("barrier.cluster.wait.aligned;"   ::: "memory");
    }
}

// ---------------- fused logits + reductions (s-halved, 2 CTAs/SM) --------
#define USTR 68
#define ZSTR2 132
__global__ __launch_bounds__(256, 2) void logits_kernel()
{
    extern __shared__ float sm[];
    float* Ut = sm;                  // [d][trow] stride USTR
    float* Zt = sm + 128*USTR;       // [d][s_local] stride ZSTR2
    int tile = blockIdx.x, b = blockIdx.y, k = blockIdx.z;
    int tid = threadIdx.x;
    int tx = tid & 15, ty = tid >> 4;     // tx: 16 s-groups of 8; ty: 16 t-groups of 4

    int t0 = tile * 64;
    const float* Ub = g_U + ((long)k*32768 + (long)b*256 + t0) * 128;
    #pragma unroll
    for (int l = 0; l < 8; l++) {
        int f = tid + l*256;
        int r = f >> 5, d4 = (f & 31) << 2;
        float4 v = *(const float4*)(Ub + r*128 + d4);
        Ut[(d4+0)*USTR + r] = v.x; Ut[(d4+1)*USTR + r] = v.y;
        Ut[(d4+2)*USTR + r] = v.z; Ut[(d4+3)*USTR + r] = v.w;
    }

    const float* Zb = g_z + (long)b * 256 * 128;
    float lsum[4], nmax[4], pos[4];
    #pragma unroll
    for (int i = 0; i < 4; i++) { lsum[i] = 0.f; nmax[i] = -3.0e38f; pos[i] = -3.0e38f; }

    for (int half = 0; half < 2; half++) {
        __syncthreads();   // prior-half compute done (and Ut load on half 0)
        #pragma unroll
        for (int l = 0; l < 16; l++) {
            int f = tid + l*256;
            int ss = f >> 5, d4 = (f & 31) << 2;
            float4 v = *(const float4*)(Zb + (long)(half*128 + ss)*128 + d4);
            Zt[(d4+0)*ZSTR2 + ss] = v.x; Zt[(d4+1)*ZSTR2 + ss] = v.y;
            Zt[(d4+2)*ZSTR2 + ss] = v.z; Zt[(d4+3)*ZSTR2 + ss] = v.w;
        }
        __syncthreads();

        unsigned long long acc2[4][4];
        #pragma unroll
        for (int i = 0; i < 4; i++)
            #pragma unroll
            for (int j = 0; j < 4; j++) acc2[i][j] = 0ULL;

        for (int d = 0; d < 128; d++) {
            float4 u = *(const float4*)&Ut[d*USTR + ty*4];
            ulonglong2 z01 = *(const ulonglong2*)&Zt[d*ZSTR2 + tx*8];
            ulonglong2 z23 = *(const ulonglong2*)&Zt[d*ZSTR2 + tx*8 + 4];
            float ua[4] = {u.x, u.y, u.z, u.w};
            #pragma unroll
            for (int i = 0; i < 4; i++) {
                unsigned long long av = pack2(ua[i]);
                FMA2(acc2[i][0], av, z01.x);
                FMA2(acc2[i][1], av, z01.y);
                FMA2(acc2[i][2], av, z23.x);
                FMA2(acc2[i][3], av, z23.y);
            }
        }

        #pragma unroll
        for (int i = 0; i < 4; i++) {
            int t = t0 + ty*4 + i;
            int spos = t + k + 1;
            float lrow[8];
            #pragma unroll
            for (int jp = 0; jp < 4; jp++) unpack2(acc2[i][jp], lrow[2*jp], lrow[2*jp+1]);
            #pragma unroll
            for (int j = 0; j < 8; j++) {
                int sg = half*128 + tx*8 + j;
                float l = lrow[j];
                lsum[i] += expf(l);
                if (sg == spos) pos[i] = l;
                else            nmax[i] = fmaxf(nmax[i], l);
            }
        }
    }

    // reduce over s within 16-lane tx groups
    float loss_tot = 0.f, acc_tot = 0.f;
    #pragma unroll
    for (int i = 0; i < 4; i++) {
        float ls = lsum[i], nm = nmax[i], ps = pos[i];
        #pragma unroll
        for (int o = 8; o; o >>= 1) {
            ls += __shfl_xor_sync(0xffffffffu, ls, o);
            nm = fmaxf(nm, __shfl_xor_sync(0xffffffffu, nm, o));
            ps = fmaxf(ps, __shfl_xor_sync(0xffffffffu, ps, o));
        }
        int t = t0 + ty*4 + i;
        if (t < TP && tx == 0) {
            loss_tot += logf(ls) - ps;
            acc_tot  += (ps >= nm) ? 1.f : 0.f;
        }
    }
    __shared__ float wl[16], wa[16];
    if (tx == 0) { wl[ty] = loss_tot; wa[ty] = acc_tot; }
    __syncthreads();
    if (tid == 0) {
        float L = 0.f, A = 0.f;
        #pragma unroll
        for (int w = 0; w < 16; w++) { L += wl[w]; A += wa[w]; }
        long bid = ((long)k*128 + b)*4 + tile;
        g_part[bid*2]   = L;
        g_part[bid*2+1] = A;
    }
}

// ---------------- final reduction ---------------------------------------
__global__ void final_kernel(float* __restrict__ out)
{
    __shared__ float sl[256], sa[256];
    int tid = threadIdx.x;
    float L = 0.f, A = 0.f;
    for (int i = tid; i < 6144; i += 256) { L += g_part[i*2]; A += g_part[i*2+1]; }
    sl[tid] = L; sa[tid] = A;
    __syncthreads();
    for (int o = 128; o; o >>= 1) {
        if (tid < o) { sl[tid] += sl[tid+o]; sa[tid] += sa[tid+o]; }
        __syncthreads();
    }
    if (tid == 0) {
        out[0] = sl[0] / (float)NROWS_L;
        out[1] = sa[0] / (float)NROWS_L * 100.f;
    }
}

// ---------------- copy z and c into d_out (8B-aligned dst) ---------------
__global__ void copyout_kernel(float* __restrict__ out)
{
    long i = (long)blockIdx.x * 256 + threadIdx.x;
    float2* dst = (float2*)(out + 2);
    const long NZ2 = 2097152;
    const long NC2 = 4194304;
    if (i < NZ2) {
        dst[i] = ((const float2*)g_z)[i];
    } else if (i < NZ2 + NC2) {
        dst[i] = ((const float2*)g_c)[i - NZ2];
    }
}

// ---------------- host launcher ------------------------------------------
extern "C" void kernel_launch(void* const* d_in, const int* in_sizes, int n_in,
                              void* d_out, int out_size)
{
    const float* rr  = (const float*)d_in[0];
    const float* w1  = (const float*)d_in[1];
    const float* b1  = (const float*)d_in[2];
    const float* w2  = (const float*)d_in[3];
    const float* b2  = (const float*)d_in[4];
    const float* Wih = (const float*)d_in[5];
    const float* Whh = (const float*)d_in[6];
    const float* bih = (const float*)d_in[7];
    const float* bhh = (const float*)d_in[8];
    const float* Wkw = (const float*)d_in[9];
    const float* Wkb = (const float*)d_in[10];

    float* out = (float*)d_out;

    float *pz, *pc, *ph1, *pgx, *pU, *pw1T, *pw2T, *pWkT;
    cudaGetSymbolAddress((void**)&pz,   g_z);
    cudaGetSymbolAddress((void**)&pc,   g_c);
    cudaGetSymbolAddress((void**)&ph1,  g_h1);
    cudaGetSymbolAddress((void**)&pgx,  g_gx);
    cudaGetSymbolAddress((void**)&pU,   g_U);
    cudaGetSymbolAddress((void**)&pw1T, g_w1T);
    cudaGetSymbolAddress((void**)&pw2T, g_w2T);
    cudaGetSymbolAddress((void**)&pWkT, g_WkT);

    cudaFuncSetAttribute(logits_kernel, cudaFuncAttributeMaxDynamicSharedMemorySize, LOG_SMEM);
    cudaFuncSetAttribute(gru_cluster,   cudaFuncAttributeMaxDynamicSharedMemorySize, GRU_SMEM);

    // 0. weight transposes
    prep_transpose<<<1536, 256>>>(w1, w2, Wkw);
    // 1. encoder layer 1 (relu)
    gemm_nt<<<dim3(2, 256, 1), 256>>>(rr, pw1T, b1, ph1, N_BT, 256, 256, 1, 0, 0, 0, 0);
    // 2. encoder layer 2 -> normalized z (mode 2 epilogue)
    gemm_nt<<<dim3(1, 256, 1), 256>>>(ph1, pw2T, b2, pz, N_BT, 128, 256, 0, 2, 0, 0, 0);
    // 3. gx = z @ W_ih^T + b_ih
    gemm_nt<<<dim3(6, 256, 1), 256>>>(pz, Wih, bih, pgx, N_BT, 768, 128, 0, 0, 0, 0, 0);
    // 4. GRU (clustered, weight-stationary)
    gru_cluster<<<128, 256, GRU_SMEM>>>(Whh, bhh);
    // 5. U[k] = rowscale10(c @ Wk_w[k] + Wk_b[k])  (mode 1 epilogue)
    gemm_nt<<<dim3(1, 256, 12), 256>>>(pc, pWkT, Wkb, pU, N_BT, 128, 256, 0, 1,
                                       32768L, 128L, (long)N_BT * 128);
    // 6. fused logits + reductions
    logits_kernel<<<dim3(4, 128, 12), 256, LOG_SMEM>>>();
    // 7. final loss/accuracy
    final_kernel<<<1, 256>>>(out);
    // 8. copy z_seq and c_seq into d_out
    copyout_kernel<<<24576, 256>>>(out);
}

// round 6
// speedup vs baseline: 1.1337x; 1.1337x over previous
#include <cuda_runtime.h>
#include <math.h>
#include <stdint.h>

// B=128, T=256, W=256, D=128, C=256, K=12, Tp=244, TEMP=0.1
#define N_BT     32768
#define TP       244
#define NROWS_L  374784
#define LOG_SMEM ((128*68 + 128*260)*4)
#define GRU_SMEM ((96*260 + 4096 + 864 + 1600 + 96)*4)
#define MMA_SMEM (18560*4)          // Abuf2+Bbuf2 (18432 fl) + bias 128 fl

// ---------------- packed f32x2 helpers (GRU / logits) --------------------
#define FMA2(d,a,b) asm("fma.rn.f32x2 %0, %1, %2, %0;" : "+l"(d) : "l"(a), "l"(b))
__device__ __forceinline__ unsigned long long pack2(float x) {
    unsigned long long r; asm("mov.b64 %0, {%1, %1};" : "=l"(r) : "f"(x)); return r;
}
__device__ __forceinline__ void unpack2(unsigned long long v, float& lo, float& hi) {
    asm("mov.b64 {%0, %1}, %2;" : "=f"(lo), "=f"(hi) : "l"(v));
}
__device__ __forceinline__ float pairsum(unsigned long long v) {
    float a, b; unpack2(v, a, b); return a + b;
}
__device__ __forceinline__ uint32_t s2u(const void* p) {
    uint32_t a; asm("{ .reg .u64 t; cvta.to.shared.u64 t, %1; cvt.u32.u64 %0, t; }" : "=r"(a) : "l"(p));
    return a;
}
__device__ __forceinline__ uint32_t mapa_u32(uint32_t addr, uint32_t rank) {
    uint32_t r; asm("mapa.shared::cluster.u32 %0, %1, %2;" : "=r"(r) : "r"(addr), "r"(rank));
    return r;
}
__device__ __forceinline__ void st_cluster_f32(uint32_t addr, float v) {
    asm volatile("st.shared::cluster.f32 [%0], %1;" :: "r"(addr), "f"(v) : "memory");
}

// ---------------- tf32 mma helpers ---------------------------------------
__device__ __forceinline__ uint32_t f2tf(float x) {
    uint32_t r; asm("cvt.rna.tf32.f32 %0, %1;" : "=r"(r) : "f"(x)); return r;
}
__device__ __forceinline__ void mma8(float* c, const uint32_t* a, const uint32_t* b) {
    asm volatile("mma.sync.aligned.m16n8k8.row.col.f32.tf32.tf32.f32 "
        "{%0,%1,%2,%3}, {%4,%5,%6,%7}, {%8,%9}, {%0,%1,%2,%3};"
        : "+f"(c[0]), "+f"(c[1]), "+f"(c[2]), "+f"(c[3])
        : "r"(a[0]), "r"(a[1]), "r"(a[2]), "r"(a[3]), "r"(b[0]), "r"(b[1]));
}

// ---------------- scratch ------------------------------------------------
__device__ __align__(16) float g_z   [4194304];   // [32768,128] normalized z
__device__ __align__(16) float g_c   [8388608];   // [32768,256] c_seq
__device__ __align__(16) float g_h1  [8388608];   // [32768,256]
__device__ __align__(16) float g_gx  [25165824];  // [32768,768]
__device__ __align__(16) float g_U   [50331648];  // [12,32768,128] rows scaled by 10/||.||
__device__ __align__(16) float g_w1T [65536];
__device__ __align__(16) float g_w2T [32768];
__device__ __align__(16) float g_WkT [393216];
__device__ __align__(16) float g_part[12288];

// ---------------- prep: transposes --------------------------------------
__global__ void prep_transpose(const float* __restrict__ w1, const float* __restrict__ w2,
                               const float* __restrict__ wk)
{
    long i = (long)blockIdx.x * 256 + threadIdx.x;
    if (i < 65536) {
        int n = (int)(i >> 8), k = (int)(i & 255);
        g_w1T[n*256 + k] = w1[k*256 + n];
    }
    if (i < 32768) {
        int n = (int)(i >> 8), k = (int)(i & 255);
        g_w2T[n*256 + k] = w2[k*128 + n];
    }
    if (i < 393216) {
        long kk = i / 32768; long r = i % 32768;
        int d = (int)(r >> 8), c = (int)(r & 255);
        g_WkT[kk*32768 + d*256 + c] = wk[kk*32768 + c*128 + d];
    }
}

// ---------------- 3xTF32 mma.sync NT-GEMM --------------------------------
// C[M,N] = A[M,K] @ B[N,K]^T + bias.  Block tile 128x128, warp tile 64x32,
// K chunked by 32, reg-prefetch double-buffered smem (stride 36: conflict-free).
// mode 0: plain(+relu); 1: rows *= 10/max(||r||,eps); 2: rows *= 1/max(||r||,eps).
// modes 1/2 require N==128 (gridDim.x==1). K%32==0.
__global__ __launch_bounds__(256, 1) void mma_gemm(
    const float* __restrict__ A, const float* __restrict__ Bm,
    const float* __restrict__ bias, float* __restrict__ Cm,
    int M, int N, int K, int relu, int mode,
    long sB, long sBias, long sC)
{
    extern __shared__ float sm[];
    float* Abuf0 = sm;            // [128][36]
    float* Abuf1 = sm + 4608;
    float* Bbuf0 = sm + 9216;
    float* Bbuf1 = sm + 13824;
    float* sbias = sm + 18432;    // [128]
    float* rs    = sm;            // overlay on Abuf0: [128][17]
    float* rinv  = sm + 2176;     // [128]

    const float* Bz = Bm  + (long)blockIdx.z * sB;
    const float* bz = bias + (long)blockIdx.z * sBias;
    float*       Cz = Cm  + (long)blockIdx.z * sC;
    int m0 = blockIdx.y * 128, n0 = blockIdx.x * 128;

    int tid = threadIdx.x;
    int wid = tid >> 5, lane = tid & 31;
    int wm = wid >> 2, wn = wid & 3;
    int gid = lane >> 2, tig = lane & 3;

    if (tid < 128) sbias[tid] = bz[n0 + tid];

    const float* Ag = A  + (long)m0 * K;
    const float* Bg = Bz + (long)n0 * K;
    int lr = tid >> 1, lc4 = (tid & 1) << 2;   // unused pattern; real below

    float c[4][4][4];
    #pragma unroll
    for (int i = 0; i < 4; i++)
        #pragma unroll
        for (int j = 0; j < 4; j++)
            #pragma unroll
            for (int q = 0; q < 4; q++) c[i][j][q] = 0.f;

    // load indices: 1024 float4 per matrix per chunk; 4 per thread
    // u = tid + l*256: row = u>>3 (0..127), c4 = u&7 (float4 within 32 cols)
    float4 ra[4], rb[4];
    #pragma unroll
    for (int l = 0; l < 4; l++) {
        int u = tid + l*256, r = u >> 3, c4 = u & 7;
        ra[l] = *(const float4*)(Ag + (long)r*K + c4*4);
        rb[l] = *(const float4*)(Bg + (long)r*K + c4*4);
    }
    #pragma unroll
    for (int l = 0; l < 4; l++) {
        int u = tid + l*256, r = u >> 3, c4 = u & 7;
        *(float4*)(Abuf0 + r*36 + c4*4) = ra[l];
        *(float4*)(Bbuf0 + r*36 + c4*4) = rb[l];
    }
    __syncthreads();

    int NC = K >> 5;
    for (int kc = 0; kc < NC; kc++) {
        const float* Ab_s = (kc & 1) ? Abuf1 : Abuf0;
        const float* Bb_s = (kc & 1) ? Bbuf1 : Bbuf0;
        bool nxt = (kc + 1 < NC);
        if (nxt) {
            int k0 = (kc + 1) * 32;
            #pragma unroll
            for (int l = 0; l < 4; l++) {
                int u = tid + l*256, r = u >> 3, c4 = u & 7;
                ra[l] = *(const float4*)(Ag + (long)r*K + k0 + c4*4);
                rb[l] = *(const float4*)(Bg + (long)r*K + k0 + c4*4);
            }
        }

        #pragma unroll
        for (int ks = 0; ks < 4; ks++) {
            int k = ks * 8;
            uint32_t ah[4][4], al[4][4];
            #pragma unroll
            for (int i = 0; i < 4; i++) {
                int r0 = wm*64 + i*16 + gid;
                float f0 = Ab_s[r0*36 + k + tig];
                float f1 = Ab_s[(r0+8)*36 + k + tig];
                float f2 = Ab_s[r0*36 + k + tig + 4];
                float f3 = Ab_s[(r0+8)*36 + k + tig + 4];
                ah[i][0] = f2tf(f0); al[i][0] = f2tf(f0 - __uint_as_float(ah[i][0]));
                ah[i][1] = f2tf(f1); al[i][1] = f2tf(f1 - __uint_as_float(ah[i][1]));
                ah[i][2] = f2tf(f2); al[i][2] = f2tf(f2 - __uint_as_float(ah[i][2]));
                ah[i][3] = f2tf(f3); al[i][3] = f2tf(f3 - __uint_as_float(ah[i][3]));
            }
            #pragma unroll
            for (int j = 0; j < 4; j++) {
                int n = wn*32 + j*8 + gid;
                float g0 = Bb_s[n*36 + k + tig];
                float g1 = Bb_s[n*36 + k + tig + 4];
                uint32_t bh[2], bl[2];
                bh[0] = f2tf(g0); bl[0] = f2tf(g0 - __uint_as_float(bh[0]));
                bh[1] = f2tf(g1); bl[1] = f2tf(g1 - __uint_as_float(bh[1]));
                #pragma unroll
                for (int i = 0; i < 4; i++) {
                    mma8(c[i][j], ah[i], bh);
                    mma8(c[i][j], ah[i], bl);
                    mma8(c[i][j], al[i], bh);
                }
            }
        }

        if (nxt) {
            float* An = (kc & 1) ? Abuf0 : Abuf1;
            float* Bn = (kc & 1) ? Bbuf0 : Bbuf1;
            #pragma unroll
            for (int l = 0; l < 4; l++) {
                int u = tid + l*256, r = u >> 3, c4 = u & 7;
                *(float4*)(An + r*36 + c4*4) = ra[l];
                *(float4*)(Bn + r*36 + c4*4) = rb[l];
            }
            __syncthreads();
        }
    }

    // epilogue: add bias
    #pragma unroll
    for (int i = 0; i < 4; i++)
        #pragma unroll
        for (int j = 0; j < 4; j++) {
            int colb = wn*32 + j*8 + tig*2;
            c[i][j][0] += sbias[colb]; c[i][j][1] += sbias[colb+1];
            c[i][j][2] += sbias[colb]; c[i][j][3] += sbias[colb+1];
        }

    if (mode == 0) {
        #pragma unroll
        for (int i = 0; i < 4; i++) {
            int r0 = m0 + wm*64 + i*16 + gid;
            #pragma unroll
            for (int j = 0; j < 4; j++) {
                int colb = n0 + wn*32 + j*8 + tig*2;
                float2 v0 = make_float2(c[i][j][0], c[i][j][1]);
                float2 v1 = make_float2(c[i][j][2], c[i][j][3]);
                if (relu) {
                    v0.x = fmaxf(v0.x, 0.f); v0.y = fmaxf(v0.y, 0.f);
                    v1.x = fmaxf(v1.x, 0.f); v1.y = fmaxf(v1.y, 0.f);
                }
                *(float2*)(Cz + (long)r0*N + colb)     = v0;
                *(float2*)(Cz + (long)(r0+8)*N + colb) = v1;
            }
        }
    } else {
        __syncthreads();   // safe to overlay rs onto Abuf0
        #pragma unroll
        for (int i = 0; i < 4; i++) {
            float ss0 = 0.f, ss1 = 0.f;
            #pragma unroll
            for (int j = 0; j < 4; j++) {
                ss0 += c[i][j][0]*c[i][j][0] + c[i][j][1]*c[i][j][1];
                ss1 += c[i][j][2]*c[i][j][2] + c[i][j][3]*c[i][j][3];
            }
            int r0 = wm*64 + i*16 + gid;
            rs[r0*17 + wn*4 + tig]     = ss0;
            rs[(r0+8)*17 + wn*4 + tig] = ss1;
        }
        __syncthreads();
        if (tid < 128) {
            float ss = 0.f;
            #pragma unroll
            for (int x = 0; x < 16; x++) ss += rs[tid*17 + x];
            float inv = 1.f / fmaxf(sqrtf(ss), 1e-12f);
            if (mode == 1) inv *= 10.f;
            rinv[tid] = inv;
        }
        __syncthreads();
        #pragma unroll
        for (int i = 0; i < 4; i++) {
            int rr = wm*64 + i*16 + gid;
            float sc0 = rinv[rr], sc1 = rinv[rr+8];
            int r0 = m0 + rr;
            #pragma unroll
            for (int j = 0; j < 4; j++) {
                int colb = n0 + wn*32 + j*8 + tig*2;
                *(float2*)(Cz + (long)r0*N + colb) =
                    make_float2(c[i][j][0]*sc0, c[i][j][1]*sc0);
                *(float2*)(Cz + (long)(r0+8)*N + colb) =
                    make_float2(c[i][j][2]*sc1, c[i][j][3]*sc1);
            }
        }
    }
}

// ---------------- GRU: weight-stationary 8-CTA clusters ------------------
__global__ __launch_bounds__(256, 1) __cluster_dims__(8, 1, 1)
void gru_cluster(const float* __restrict__ Whh, const float* __restrict__ bhh)
{
    extern __shared__ float s[];
    float* W_s  = s;                       // [96][260]
    float* hb   = s + 96*260;              // [2][8][256]
    float* gh_s = hb + 4096;               // [96][9]
    float* gx_s = gh_s + 864;              // [2][8][100]
    float* bh_s = gx_s + 1600;             // [96]

    int tid  = threadIdx.x;
    int rank = blockIdx.x & 7;
    int cl   = blockIdx.x >> 3;
    int co   = rank * 32;
    int b0   = cl * 8;

    for (int i = tid; i < 96*256; i += 256) {
        int r = i >> 8, k = i & 255;
        int grow = (r >> 5)*256 + co + (r & 31);
        W_s[r*260 + k] = Whh[grow*256 + k];
    }
    if (tid < 96) {
        int grow = (tid >> 5)*256 + co + (tid & 31);
        bh_s[tid] = bhh[grow];
    }
    for (int i = tid; i < 2048; i += 256) hb[i] = 0.f;

    if (tid >= 192) {
        int f = tid - 192;
        for (int i = f; i < 768; i += 64) {
            int b = i / 96, pos = i - b*96;
            gx_s[b*100 + pos] =
                g_gx[((long)(b0+b)*256 + 0)*768 + (pos>>5)*256 + co + (pos&31)];
        }
    }

    int ub = tid >> 5, uc = tid & 31;
    uint32_t local_addr = s2u(hb) + (uint32_t)((ub*256 + co + uc) * 4);
    uint32_t radr[8];
    #pragma unroll
    for (int r = 0; r < 8; r++) radr[r] = mapa_u32(local_addr, r);
    float h_old = 0.f;
    float* cptr = g_c + ((long)(b0+ub)*256)*256 + co + uc;

    int g = tid >> 1, bbase = (tid & 1) * 4;
    __syncthreads();

    for (int t = 0; t < 256; t++) {
        int p = t & 1, pn = p ^ 1;
        const float* hcur = hb + p*2048;

        if (tid < 192) {
            const float* wr = W_s + g*260;
            const float* h0 = hcur + (bbase+0)*256;
            const float* h1 = hcur + (bbase+1)*256;
            const float* h2 = hcur + (bbase+2)*256;
            const float* h3 = hcur + (bbase+3)*256;
            unsigned long long a0=0ULL, a1=0ULL, a2=0ULL, a3=0ULL;
            #pragma unroll 4
            for (int k = 0; k < 64; k++) {
                ulonglong2 w = *(const ulonglong2*)(wr + k*4);
                ulonglong2 x;
                x = *(const ulonglong2*)(h0 + k*4); FMA2(a0, w.x, x.x); FMA2(a0, w.y, x.y);
                x = *(const ulonglong2*)(h1 + k*4); FMA2(a1, w.x, x.x); FMA2(a1, w.y, x.y);
                x = *(const ulonglong2*)(h2 + k*4); FMA2(a2, w.x, x.x); FMA2(a2, w.y, x.y);
                x = *(const ulonglong2*)(h3 + k*4); FMA2(a3, w.x, x.x); FMA2(a3, w.y, x.y);
            }
            gh_s[g*9 + bbase+0] = pairsum(a0);
            gh_s[g*9 + bbase+1] = pairsum(a1);
            gh_s[g*9 + bbase+2] = pairsum(a2);
            gh_s[g*9 + bbase+3] = pairsum(a3);
        } else if (t < 255) {
            int f = tid - 192;
            float* dst = gx_s + pn*800;
            for (int i = f; i < 768; i += 64) {
                int b = i / 96, pos = i - b*96;
                dst[b*100 + pos] =
                    g_gx[((long)(b0+b)*256 + (t+1))*768 + (pos>>5)*256 + co + (pos&31)];
            }
        }
        __syncthreads();

        {
            const float* gxb = gx_s + p*800 + ub*100;
            float xr = gxb[uc], xz = gxb[32+uc], xn = gxb[64+uc];
            float hr = gh_s[uc*9 + ub]        + bh_s[uc];
            float hz = gh_s[(32+uc)*9 + ub]   + bh_s[32+uc];
            float hn = gh_s[(64+uc)*9 + ub]   + bh_s[64+uc];
            float rg = 1.f / (1.f + expf(-(xr + hr)));
            float zg = 1.f / (1.f + expf(-(xz + hz)));
            float ng = tanhf(xn + rg*hn);
            float hnew = (1.f - zg)*ng + zg*h_old;
            h_old = hnew;
            uint32_t off = (uint32_t)(pn * 8192);
            #pragma unroll
            for (int r = 0; r < 8; r++) st_cluster_f32(radr[r] + off, hnew);
            cptr[t*256] = hnew;
        }
        asm volatile("barrier.cluster.arrive.aligned;" ::: "memory");
        asm volatile("barrier.cluster.wait.aligned;"   ::: "memory");
    }
}

// ---------------- fused logits + reductions ------------------------------
#define ZSTR 260
#define USTR 68
__global__ __launch_bounds__(256) void logits_kernel()
{
    extern __shared__ float sm[];
    float* Ut = sm;                  // [d][row] stride USTR
    float* Zt = sm + 128*USTR;       // [d][s]   stride ZSTR
    int tile = blockIdx.x, b = blockIdx.y, k = blockIdx.z;
    int tid = threadIdx.x;
    int tx = tid & 31, ty = tid >> 5;

    const float* Zb = g_z + (long)b * 256 * 128;
    #pragma unroll
    for (int l = 0; l < 32; l++) {
        int f = tid + l*256;
        int ss = f >> 5, d4 = (f & 31) << 2;
        float4 v = *(const float4*)(Zb + ss*128 + d4);
        Zt[(d4+0)*ZSTR + ss] = v.x; Zt[(d4+1)*ZSTR + ss] = v.y;
        Zt[(d4+2)*ZSTR + ss] = v.z; Zt[(d4+3)*ZSTR + ss] = v.w;
    }
    int t0 = tile * 64;
    const float* Ub = g_U + ((long)k*32768 + (long)b*256 + t0) * 128;
    #pragma unroll
    for (int l = 0; l < 8; l++) {
        int f = tid + l*256;
        int r = f >> 5, d4 = (f & 31) << 2;
        float4 v = *(const float4*)(Ub + r*128 + d4);
        Ut[(d4+0)*USTR + r] = v.x; Ut[(d4+1)*USTR + r] = v.y;
        Ut[(d4+2)*USTR + r] = v.z; Ut[(d4+3)*USTR + r] = v.w;
    }
    __syncthreads();

    unsigned long long acc2[8][4];
    #pragma unroll
    for (int i = 0; i < 8; i++)
        #pragma unroll
        for (int j = 0; j < 4; j++) acc2[i][j] = 0ULL;

    for (int d = 0; d < 128; d++) {
        float4 u0 = *(const float4*)&Ut[d*USTR + ty*8];
        float4 u1 = *(const float4*)&Ut[d*USTR + ty*8 + 4];
        ulonglong2 z01 = *(const ulonglong2*)&Zt[d*ZSTR + tx*8];
        ulonglong2 z23 = *(const ulonglong2*)&Zt[d*ZSTR + tx*8 + 4];
        float ua[8] = {u0.x,u0.y,u0.z,u0.w,u1.x,u1.y,u1.z,u1.w};
        #pragma unroll
        for (int i = 0; i < 8; i++) {
            unsigned long long av = pack2(ua[i]);
            FMA2(acc2[i][0], av, z01.x);
            FMA2(acc2[i][1], av, z01.y);
            FMA2(acc2[i][2], av, z23.x);
            FMA2(acc2[i][3], av, z23.y);
        }
    }

    float loss_tot = 0.f, acc_tot = 0.f;
    #pragma unroll
    for (int i = 0; i < 8; i++) {
        int t = t0 + ty*8 + i;
        bool valid = (t < TP);
        int spos = t + k + 1;
        float lrow[8];
        #pragma unroll
        for (int jp = 0; jp < 4; jp++) unpack2(acc2[i][jp], lrow[2*jp], lrow[2*jp+1]);
        float lsum = 0.f, nmax = -3.0e38f, pos = -3.0e38f;
        #pragma unroll
        for (int j = 0; j < 8; j++) {
            int sidx = tx*8 + j;
            float l = lrow[j];
            lsum += expf(l);
            if (sidx == spos) pos = l;
            else              nmax = fmaxf(nmax, l);
        }
        #pragma unroll
        for (int o = 16; o; o >>= 1) {
            lsum += __shfl_xor_sync(0xffffffffu, lsum, o);
            nmax = fmaxf(nmax, __shfl_xor_sync(0xffffffffu, nmax, o));
            pos  = fmaxf(pos,  __shfl_xor_sync(0xffffffffu, pos,  o));
        }
        if (valid && tx == 0) {
            loss_tot += logf(lsum) - pos;
            acc_tot  += (pos >= nmax) ? 1.f : 0.f;
        }
    }
    __shared__ float wl[8], wa[8];
    if (tx == 0) { wl[ty] = loss_tot; wa[ty] = acc_tot; }
    __syncthreads();
    if (tid == 0) {
        float L = 0.f, A = 0.f;
        #pragma unroll
        for (int w = 0; w < 8; w++) { L += wl[w]; A += wa[w]; }
        long bid = ((long)k*128 + b)*4 + tile;
        g_part[bid*2]   = L;
        g_part[bid*2+1] = A;
    }
}

// ---------------- final reduction ---------------------------------------
__global__ void final_kernel(float* __restrict__ out)
{
    __shared__ float sl[256], sa[256];
    int tid = threadIdx.x;
    float L = 0.f, A = 0.f;
    for (int i = tid; i < 6144; i += 256) { L += g_part[i*2]; A += g_part[i*2+1]; }
    sl[tid] = L; sa[tid] = A;
    __syncthreads();
    for (int o = 128; o; o >>= 1) {
        if (tid < o) { sl[tid] += sl[tid+o]; sa[tid] += sa[tid+o]; }
        __syncthreads();
    }
    if (tid == 0) {
        out[0] = sl[0] / (float)NROWS_L;
        out[1] = sa[0] / (float)NROWS_L * 100.f;
    }
}

// ---------------- copy z and c into d_out (8B-aligned dst) ---------------
__global__ void copyout_kernel(float* __restrict__ out)
{
    long i = (long)blockIdx.x * 256 + threadIdx.x;
    float2* dst = (float2*)(out + 2);
    const long NZ2 = 2097152;
    const long NC2 = 4194304;
    if (i < NZ2) {
        dst[i] = ((const float2*)g_z)[i];
    } else if (i < NZ2 + NC2) {
        dst[i] = ((const float2*)g_c)[i - NZ2];
    }
}

// ---------------- host launcher ------------------------------------------
extern "C" void kernel_launch(void* const* d_in, const int* in_sizes, int n_in,
                              void* d_out, int out_size)
{
    const float* rr  = (const float*)d_in[0];
    const float* w1  = (const float*)d_in[1];
    const float* b1  = (const float*)d_in[2];
    const float* w2  = (const float*)d_in[3];
    const float* b2  = (const float*)d_in[4];
    const float* Wih = (const float*)d_in[5];
    const float* Whh = (const float*)d_in[6];
    const float* bih = (const float*)d_in[7];
    const float* bhh = (const float*)d_in[8];
    const float* Wkw = (const float*)d_in[9];
    const float* Wkb = (const float*)d_in[10];

    float* out = (float*)d_out;

    float *pz, *pc, *ph1, *pgx, *pU, *pw1T, *pw2T, *pWkT;
    cudaGetSymbolAddress((void**)&pz,   g_z);
    cudaGetSymbolAddress((void**)&pc,   g_c);
    cudaGetSymbolAddress((void**)&ph1,  g_h1);
    cudaGetSymbolAddress((void**)&pgx,  g_gx);
    cudaGetSymbolAddress((void**)&pU,   g_U);
    cudaGetSymbolAddress((void**)&pw1T, g_w1T);
    cudaGetSymbolAddress((void**)&pw2T, g_w2T);
    cudaGetSymbolAddress((void**)&pWkT, g_WkT);

    cudaFuncSetAttribute(logits_kernel, cudaFuncAttributeMaxDynamicSharedMemorySize, LOG_SMEM);
    cudaFuncSetAttribute(gru_cluster,   cudaFuncAttributeMaxDynamicSharedMemorySize, GRU_SMEM);
    cudaFuncSetAttribute(mma_gemm,      cudaFuncAttributeMaxDynamicSharedMemorySize, MMA_SMEM);

    // 0. weight transposes
    prep_transpose<<<1536, 256>>>(w1, w2, Wkw);
    // 1. encoder layer 1 (relu)
    mma_gemm<<<dim3(2, 256, 1), 256, MMA_SMEM>>>(
        rr, pw1T, b1, ph1, N_BT, 256, 256, 1, 0, 0, 0, 0);
    // 2. encoder layer 2 -> normalized z (mode 2)
    mma_gemm<<<dim3(1, 256, 1), 256, MMA_SMEM>>>(
        ph1, pw2T, b2, pz, N_BT, 128, 256, 0, 2, 0, 0, 0);
    // 3. gx = z @ W_ih^T + b_ih
    mma_gemm<<<dim3(6, 256, 1), 256, MMA_SMEM>>>(
        pz, Wih, bih, pgx, N_BT, 768, 128, 0, 0, 0, 0, 0);
    // 4. GRU (clustered, weight-stationary)
    gru_cluster<<<128, 256, GRU_SMEM>>>(Whh, bhh);
    // 5. U[k] = rowscale10(c @ Wk_w[k] + Wk_b[k])  (mode 1)
    mma_gemm<<<dim3(1, 256, 12), 256, MMA_SMEM>>>(
        pc, pWkT, Wkb, pU, N_BT, 128, 256, 0, 1,
        32768L, 128L, (long)N_BT * 128);
    // 6. fused logits + reductions
    logits_kernel<<<dim3(4, 128, 12), 256, LOG_SMEM>>>();
    // 7. final loss/accuracy
    final_kernel<<<1, 256>>>(out);
    // 8. copy z_seq and c_seq into d_out
    copyout_kernel<<<24576, 256>>>(out);
}

// round 7
// speedup vs baseline: 1.3190x; 1.1634x over previous
#include <cuda_runtime.h>
#include <math.h>
#include <stdint.h>

// B=128, T=256, W=256, D=128, C=256, K=12, Tp=244, TEMP=0.1
#define N_BT     32768
#define TP       244
#define NROWS_L  374784
#define GRU_SMEM ((96*260 + 4096 + 864 + 1600 + 96)*4)
// gemm smem: 2 buf x 4 arrays x 128x36 words + 128 bias
#define GEMM_SMEM ((2*4*4608 + 128)*4)
// logits smem: 2 buf x (Uh,Ul 64x36 + Zh,Zl 256x36) + red 3x256 + pad
#define LOG_BUF   (2*2304 + 2*9216)
#define LOG_SMEM  ((2*LOG_BUF + 3*256 + 64)*4)

// ---------------- packed f32x2 helpers (GRU) -----------------------------
#define FMA2(d,a,b) asm("fma.rn.f32x2 %0, %1, %2, %0;" : "+l"(d) : "l"(a), "l"(b))
__device__ __forceinline__ void unpack2(unsigned long long v, float& lo, float& hi) {
    asm("mov.b64 {%0, %1}, %2;" : "=f"(lo), "=f"(hi) : "l"(v));
}
__device__ __forceinline__ float pairsum(unsigned long long v) {
    float a, b; unpack2(v, a, b); return a + b;
}
__device__ __forceinline__ uint32_t s2u(const void* p) {
    uint32_t a; asm("{ .reg .u64 t; cvta.to.shared.u64 t, %1; cvt.u32.u64 %0, t; }" : "=r"(a) : "l"(p));
    return a;
}
__device__ __forceinline__ uint32_t mapa_u32(uint32_t addr, uint32_t rank) {
    uint32_t r; asm("mapa.shared::cluster.u32 %0, %1, %2;" : "=r"(r) : "r"(addr), "r"(rank));
    return r;
}
__device__ __forceinline__ void st_cluster_f32(uint32_t addr, float v) {
    asm volatile("st.shared::cluster.f32 [%0], %1;" :: "r"(addr), "f"(v) : "memory");
}

// ---------------- tf32 mma helpers ---------------------------------------
__device__ __forceinline__ uint32_t f2tf(float x) {
    uint32_t r; asm("cvt.rna.tf32.f32 %0, %1;" : "=r"(r) : "f"(x)); return r;
}
__device__ __forceinline__ void cvt_hl(float4 x, uint4& h, uint4& l) {
    h.x = f2tf(x.x); l.x = f2tf(x.x - __uint_as_float(h.x));
    h.y = f2tf(x.y); l.y = f2tf(x.y - __uint_as_float(h.y));
    h.z = f2tf(x.z); l.z = f2tf(x.z - __uint_as_float(h.z));
    h.w = f2tf(x.w); l.w = f2tf(x.w - __uint_as_float(h.w));
}
__device__ __forceinline__ void mma8(float* c, const uint32_t* a, const uint32_t* b) {
    asm volatile("mma.sync.aligned.m16n8k8.row.col.f32.tf32.tf32.f32 "
        "{%0,%1,%2,%3}, {%4,%5,%6,%7}, {%8,%9}, {%0,%1,%2,%3};"
        : "+f"(c[0]), "+f"(c[1]), "+f"(c[2]), "+f"(c[3])
        : "r"(a[0]), "r"(a[1]), "r"(a[2]), "r"(a[3]), "r"(b[0]), "r"(b[1]));
}

// ---------------- scratch ------------------------------------------------
__device__ __align__(16) float g_z   [4194304];   // [32768,128] normalized z
__device__ __align__(16) float g_c   [8388608];   // [32768,256] c_seq
__device__ __align__(16) float g_h1  [8388608];   // [32768,256]
__device__ __align__(16) float g_gx  [25165824];  // [32768,768]
__device__ __align__(16) float g_U   [50331648];  // [12,32768,128] rows scaled by 10/||.||
__device__ __align__(16) float g_w1T [65536];
__device__ __align__(16) float g_w2T [32768];
__device__ __align__(16) float g_WkT [393216];
__device__ __align__(16) float g_part[12288];

// ---------------- prep: transposes --------------------------------------
__global__ void prep_transpose(const float* __restrict__ w1, const float* __restrict__ w2,
                               const float* __restrict__ wk)
{
    long i = (long)blockIdx.x * 256 + threadIdx.x;
    if (i < 65536) {
        int n = (int)(i >> 8), k = (int)(i & 255);
        g_w1T[n*256 + k] = w1[k*256 + n];
    }
    if (i < 32768) {
        int n = (int)(i >> 8), k = (int)(i & 255);
        g_w2T[n*256 + k] = w2[k*128 + n];
    }
    if (i < 393216) {
        long kk = i / 32768; long r = i % 32768;
        int d = (int)(r >> 8), c = (int)(r & 255);
        g_WkT[kk*32768 + d*256 + c] = wk[kk*32768 + c*128 + d];
    }
}

// ---------------- 3xTF32 mma.sync NT-GEMM (hi/lo staged in smem) ---------
// C[M,N] = A[M,K] @ B[N,K]^T + bias. Block tile 128x128, warp tile 64x32,
// K chunked by 32, hi/lo split done at staging. K%32==0.
// mode 0: plain(+relu); 1: rows *= 10/max(||r||,eps); 2: rows *= 1/..; need N==128.
__global__ __launch_bounds__(256, 1) void mma_gemm(
    const float* __restrict__ A, const float* __restrict__ Bm,
    const float* __restrict__ bias, float* __restrict__ Cm,
    int M, int N, int K, int relu, int mode,
    long sB, long sBias, long sC)
{
    extern __shared__ uint32_t smu[];
    // buffer b base = b*18432: Ah +0, Al +4608, Bh +9216, Bl +13824
    float* sbias = (float*)(smu + 36864);
    float* rs    = (float*)smu;          // overlay [128][17]
    float* rinv  = (float*)(smu + 2176);

    const float* Bz = Bm  + (long)blockIdx.z * sB;
    const float* bz = bias + (long)blockIdx.z * sBias;
    float*       Cz = Cm  + (long)blockIdx.z * sC;
    int m0 = blockIdx.y * 128, n0 = blockIdx.x * 128;

    int tid = threadIdx.x;
    int wid = tid >> 5, lane = tid & 31;
    int wm = wid >> 2, wn = wid & 3;
    int gid = lane >> 2, tig = lane & 3;

    if (tid < 128) sbias[tid] = bz[n0 + tid];

    const float* Ag = A  + (long)m0 * K;
    const float* Bg = Bz + (long)n0 * K;

    float c[4][4][4];
    #pragma unroll
    for (int i = 0; i < 4; i++)
        #pragma unroll
        for (int j = 0; j < 4; j++)
            #pragma unroll
            for (int q = 0; q < 4; q++) c[i][j][q] = 0.f;

    float4 ra[4], rb[4];
    #pragma unroll
    for (int l = 0; l < 4; l++) {
        int u = tid + l*256, r = u >> 3, c4 = u & 7;
        ra[l] = *(const float4*)(Ag + (long)r*K + c4*4);
        rb[l] = *(const float4*)(Bg + (long)r*K + c4*4);
    }
    #pragma unroll
    for (int l = 0; l < 4; l++) {
        int u = tid + l*256, r = u >> 3, c4 = u & 7;
        uint4 h, lo;
        cvt_hl(ra[l], h, lo);
        *(uint4*)(smu + 0    + r*36 + c4*4) = h;
        *(uint4*)(smu + 4608 + r*36 + c4*4) = lo;
        cvt_hl(rb[l], h, lo);
        *(uint4*)(smu + 9216  + r*36 + c4*4) = h;
        *(uint4*)(smu + 13824 + r*36 + c4*4) = lo;
    }
    __syncthreads();

    int NC = K >> 5;
    for (int kc = 0; kc < NC; kc++) {
        const uint32_t* base = smu + (kc & 1)*18432;
        bool nxt = (kc + 1 < NC);
        if (nxt) {
            int k0 = (kc + 1) * 32;
            #pragma unroll
            for (int l = 0; l < 4; l++) {
                int u = tid + l*256, r = u >> 3, c4 = u & 7;
                ra[l] = *(const float4*)(Ag + (long)r*K + k0 + c4*4);
                rb[l] = *(const float4*)(Bg + (long)r*K + k0 + c4*4);
            }
        }
        #pragma unroll
        for (int ks = 0; ks < 4; ks++) {
            int k = ks * 8;
            uint32_t ah[4][4], al[4][4];
            #pragma unroll
            for (int i = 0; i < 4; i++) {
                int r0 = wm*64 + i*16 + gid;
                ah[i][0] = base[r0*36 + k + tig];
                ah[i][1] = base[(r0+8)*36 + k + tig];
                ah[i][2] = base[r0*36 + k + tig + 4];
                ah[i][3] = base[(r0+8)*36 + k + tig + 4];
                al[i][0] = base[4608 + r0*36 + k + tig];
                al[i][1] = base[4608 + (r0+8)*36 + k + tig];
                al[i][2] = base[4608 + r0*36 + k + tig + 4];
                al[i][3] = base[4608 + (r0+8)*36 + k + tig + 4];
            }
            #pragma unroll
            for (int j = 0; j < 4; j++) {
                int n = wn*32 + j*8 + gid;
                uint32_t bh[2], bl[2];
                bh[0] = base[9216 + n*36 + k + tig];
                bh[1] = base[9216 + n*36 + k + tig + 4];
                bl[0] = base[13824 + n*36 + k + tig];
                bl[1] = base[13824 + n*36 + k + tig + 4];
                #pragma unroll
                for (int i = 0; i < 4; i++) {
                    mma8(c[i][j], ah[i], bh);
                    mma8(c[i][j], ah[i], bl);
                    mma8(c[i][j], al[i], bh);
                }
            }
        }
        if (nxt) {
            uint32_t* nb = smu + ((kc + 1) & 1)*18432;
            #pragma unroll
            for (int l = 0; l < 4; l++) {
                int u = tid + l*256, r = u >> 3, c4 = u & 7;
                uint4 h, lo;
                cvt_hl(ra[l], h, lo);
                *(uint4*)(nb + 0    + r*36 + c4*4) = h;
                *(uint4*)(nb + 4608 + r*36 + c4*4) = lo;
                cvt_hl(rb[l], h, lo);
                *(uint4*)(nb + 9216  + r*36 + c4*4) = h;
                *(uint4*)(nb + 13824 + r*36 + c4*4) = lo;
            }
            __syncthreads();
        }
    }

    // epilogue: bias
    #pragma unroll
    for (int i = 0; i < 4; i++)
        #pragma unroll
        for (int j = 0; j < 4; j++) {
            int colb = wn*32 + j*8 + tig*2;
            c[i][j][0] += sbias[colb]; c[i][j][1] += sbias[colb+1];
            c[i][j][2] += sbias[colb]; c[i][j][3] += sbias[colb+1];
        }

    if (mode == 0) {
        #pragma unroll
        for (int i = 0; i < 4; i++) {
            int r0 = m0 + wm*64 + i*16 + gid;
            #pragma unroll
            for (int j = 0; j < 4; j++) {
                int colb = n0 + wn*32 + j*8 + tig*2;
                float2 v0 = make_float2(c[i][j][0], c[i][j][1]);
                float2 v1 = make_float2(c[i][j][2], c[i][j][3]);
                if (relu) {
                    v0.x = fmaxf(v0.x, 0.f); v0.y = fmaxf(v0.y, 0.f);
                    v1.x = fmaxf(v1.x, 0.f); v1.y = fmaxf(v1.y, 0.f);
                }
                *(float2*)(Cz + (long)r0*N + colb)     = v0;
                *(float2*)(Cz + (long)(r0+8)*N + colb) = v1;
            }
        }
    } else {
        __syncthreads();
        #pragma unroll
        for (int i = 0; i < 4; i++) {
            float ss0 = 0.f, ss1 = 0.f;
            #pragma unroll
            for (int j = 0; j < 4; j++) {
                ss0 += c[i][j][0]*c[i][j][0] + c[i][j][1]*c[i][j][1];
                ss1 += c[i][j][2]*c[i][j][2] + c[i][j][3]*c[i][j][3];
            }
            int r0 = wm*64 + i*16 + gid;
            rs[r0*17 + wn*4 + tig]     = ss0;
            rs[(r0+8)*17 + wn*4 + tig] = ss1;
        }
        __syncthreads();
        if (tid < 128) {
            float ss = 0.f;
            #pragma unroll
            for (int x = 0; x < 16; x++) ss += rs[tid*17 + x];
            float inv = 1.f / fmaxf(sqrtf(ss), 1e-12f);
            if (mode == 1) inv *= 10.f;
            rinv[tid] = inv;
        }
        __syncthreads();
        #pragma unroll
        for (int i = 0; i < 4; i++) {
            int rr = wm*64 + i*16 + gid;
            float sc0 = rinv[rr], sc1 = rinv[rr+8];
            int r0 = m0 + rr;
            #pragma unroll
            for (int j = 0; j < 4; j++) {
                int colb = n0 + wn*32 + j*8 + tig*2;
                *(float2*)(Cz + (long)r0*N + colb) =
                    make_float2(c[i][j][0]*sc0, c[i][j][1]*sc0);
                *(float2*)(Cz + (long)(r0+8)*N + colb) =
                    make_float2(c[i][j][2]*sc1, c[i][j][3]*sc1);
            }
        }
    }
}

// ---------------- logits via 3xTF32 mma + fused reductions ---------------
// grid (4 t-tiles, 128 b, 12 k); block 256 (8 warps = 2 wm x 4 wn).
// Block tile: 64(t) x 256(s) x 128(d); warp tile 32x64; K chunks of 32.
__global__ __launch_bounds__(256, 1) void logits_mma()
{
    extern __shared__ uint32_t smu[];
    // buffer base = buf*LOG_BUF: Uh +0 (2304), Ul +2304, Zh +4608 (9216), Zl +13824
    float* redL = (float*)(smu + 2*LOG_BUF);
    float* redM = redL + 256;
    float* redP = redM + 256;
    float* wred = redP + 256;     // [32]

    int tile = blockIdx.x, b = blockIdx.y, kk = blockIdx.z;
    int t0 = tile * 64;
    int tid = threadIdx.x;
    int wid = tid >> 5, lane = tid & 31;
    int wm = wid >> 2, wn = wid & 3;
    int gid = lane >> 2, tig = lane & 3;

    const float* Ug = g_U + ((long)kk*32768 + (long)b*256 + t0) * 128;
    const float* Zg = g_z + (long)b * 32768;

    float c[2][8][4];
    #pragma unroll
    for (int i = 0; i < 2; i++)
        #pragma unroll
        for (int j = 0; j < 8; j++)
            #pragma unroll
            for (int q = 0; q < 4; q++) c[i][j][q] = 0.f;

    float4 rz[8], ru[2];
    #pragma unroll
    for (int l = 0; l < 8; l++) {
        int u = tid + l*256, r = u >> 3, c4 = u & 7;
        rz[l] = *(const float4*)(Zg + (long)r*128 + c4*4);
    }
    #pragma unroll
    for (int l = 0; l < 2; l++) {
        int u = tid + l*256, r = u >> 3, c4 = u & 7;
        ru[l] = *(const float4*)(Ug + (long)r*128 + c4*4);
    }
    #pragma unroll
    for (int l = 0; l < 8; l++) {
        int u = tid + l*256, r = u >> 3, c4 = u & 7;
        uint4 h, lo; cvt_hl(rz[l], h, lo);
        *(uint4*)(smu + 4608  + r*36 + c4*4) = h;
        *(uint4*)(smu + 13824 + r*36 + c4*4) = lo;
    }
    #pragma unroll
    for (int l = 0; l < 2; l++) {
        int u = tid + l*256, r = u >> 3, c4 = u & 7;
        uint4 h, lo; cvt_hl(ru[l], h, lo);
        *(uint4*)(smu + 0    + r*36 + c4*4) = h;
        *(uint4*)(smu + 2304 + r*36 + c4*4) = lo;
    }
    __syncthreads();

    #pragma unroll
    for (int kc = 0; kc < 4; kc++) {
        const uint32_t* base = smu + (kc & 1)*LOG_BUF;
        bool nxt = (kc < 3);
        if (nxt) {
            int k0 = (kc + 1) * 32;
            #pragma unroll
            for (int l = 0; l < 8; l++) {
                int u = tid + l*256, r = u >> 3, c4 = u & 7;
                rz[l] = *(const float4*)(Zg + (long)r*128 + k0 + c4*4);
            }
            #pragma unroll
            for (int l = 0; l < 2; l++) {
                int u = tid + l*256, r = u >> 3, c4 = u & 7;
                ru[l] = *(const float4*)(Ug + (long)r*128 + k0 + c4*4);
            }
        }
        #pragma unroll
        for (int ks = 0; ks < 4; ks++) {
            int k = ks * 8;
            uint32_t ah[2][4], al[2][4];
            #pragma unroll
            for (int i = 0; i < 2; i++) {
                int r0 = wm*32 + i*16 + gid;
                ah[i][0] = base[r0*36 + k + tig];
                ah[i][1] = base[(r0+8)*36 + k + tig];
                ah[i][2] = base[r0*36 + k + tig + 4];
                ah[i][3] = base[(r0+8)*36 + k + tig + 4];
                al[i][0] = base[2304 + r0*36 + k + tig];
                al[i][1] = base[2304 + (r0+8)*36 + k + tig];
                al[i][2] = base[2304 + r0*36 + k + tig + 4];
                al[i][3] = base[2304 + (r0+8)*36 + k + tig + 4];
            }
            #pragma unroll
            for (int j = 0; j < 8; j++) {
                int n = wn*64 + j*8 + gid;
                uint32_t bh[2], bl[2];
                bh[0] = base[4608 + n*36 + k + tig];
                bh[1] = base[4608 + n*36 + k + tig + 4];
                bl[0] = base[13824 + n*36 + k + tig];
                bl[1] = base[13824 + n*36 + k + tig + 4];
                #pragma unroll
                for (int i = 0; i < 2; i++) {
                    mma8(c[i][j], ah[i], bh);
                    mma8(c[i][j], ah[i], bl);
                    mma8(c[i][j], al[i], bh);
                }
            }
        }
        if (nxt) {
            uint32_t* nb = smu + ((kc + 1) & 1)*LOG_BUF;
            #pragma unroll
            for (int l = 0; l < 8; l++) {
                int u = tid + l*256, r = u >> 3, c4 = u & 7;
                uint4 h, lo; cvt_hl(rz[l], h, lo);
                *(uint4*)(nb + 4608  + r*36 + c4*4) = h;
                *(uint4*)(nb + 13824 + r*36 + c4*4) = lo;
            }
            #pragma unroll
            for (int l = 0; l < 2; l++) {
                int u = tid + l*256, r = u >> 3, c4 = u & 7;
                uint4 h, lo; cvt_hl(ru[l], h, lo);
                *(uint4*)(nb + 0    + r*36 + c4*4) = h;
                *(uint4*)(nb + 2304 + r*36 + c4*4) = lo;
            }
            __syncthreads();
        }
    }

    // fragment-level reduction over s (16 cols per lane per row)
    #pragma unroll
    for (int i = 0; i < 2; i++) {
        #pragma unroll
        for (int sub = 0; sub < 2; sub++) {
            int rrow = wm*32 + i*16 + sub*8 + gid;       // local t row
            int spos = t0 + rrow + kk + 1;               // global s of positive
            float lsum = 0.f, nmax = -3.0e38f, pos = -3.0e38f;
            #pragma unroll
            for (int j = 0; j < 8; j++) {
                #pragma unroll
                for (int p = 0; p < 2; p++) {
                    int col = wn*64 + j*8 + tig*2 + p;
                    float l = c[i][j][sub*2 + p];
                    lsum += __expf(l);
                    if (col == spos) pos = l;
                    else             nmax = fmaxf(nmax, l);
                }
            }
            #pragma unroll
            for (int o = 1; o <= 2; o <<= 1) {
                lsum += __shfl_xor_sync(0xffffffffu, lsum, o);
                nmax = fmaxf(nmax, __shfl_xor_sync(0xffffffffu, nmax, o));
                pos  = fmaxf(pos,  __shfl_xor_sync(0xffffffffu, pos,  o));
            }
            if (tig == 0) {
                redL[wn*64 + rrow] = lsum;
                redM[wn*64 + rrow] = nmax;
                redP[wn*64 + rrow] = pos;
            }
        }
    }
    __syncthreads();

    float loss_tot = 0.f, acc_tot = 0.f;
    if (tid < 64) {
        float ls = redL[tid] + redL[64+tid] + redL[128+tid] + redL[192+tid];
        float nm = fmaxf(fmaxf(redM[tid], redM[64+tid]), fmaxf(redM[128+tid], redM[192+tid]));
        float ps = fmaxf(fmaxf(redP[tid], redP[64+tid]), fmaxf(redP[128+tid], redP[192+tid]));
        int t = t0 + tid;
        if (t < TP) {
            loss_tot = logf(ls) - ps;
            acc_tot  = (ps >= nm) ? 1.f : 0.f;
        }
    }
    if (wid < 2) {
        #pragma unroll
        for (int o = 16; o; o >>= 1) {
            loss_tot += __shfl_xor_sync(0xffffffffu, loss_tot, o);
            acc_tot  += __shfl_xor_sync(0xffffffffu, acc_tot,  o);
        }
        if (lane == 0) { wred[wid*2] = loss_tot; wred[wid*2+1] = acc_tot; }
    }
    __syncthreads();
    if (tid == 0) {
        long bid = ((long)kk*128 + b)*4 + tile;
        g_part[bid*2]   = wred[0] + wred[2];
        g_part[bid*2+1] = wred[1] + wred[3];
    }
}

// ---------------- GRU: weight-stationary 8-CTA clusters ------------------
__global__ __launch_bounds__(256, 1) __cluster_dims__(8, 1, 1)
void gru_cluster(const float* __restrict__ Whh, const float* __restrict__ bhh)
{
    extern __shared__ float s[];
    float* W_s  = s;                       // [96][260]
    float* hb   = s + 96*260;              // [2][8][256]
    float* gh_s = hb + 4096;               // [96][9]
    float* gx_s = gh_s + 864;              // [2][8][100]
    float* bh_s = gx_s + 1600;             // [96]

    int tid  = threadIdx.x;
    int rank = blockIdx.x & 7;
    int cl   = blockIdx.x >> 3;
    int co   = rank * 32;
    int b0   = cl * 8;

    for (int i = tid; i < 96*256; i += 256) {
        int r = i >> 8, k = i & 255;
        int grow = (r >> 5)*256 + co + (r & 31);
        W_s[r*260 + k] = Whh[grow*256 + k];
    }
    if (tid < 96) {
        int grow = (tid >> 5)*256 + co + (tid & 31);
        bh_s[tid] = bhh[grow];
    }
    for (int i = tid; i < 2048; i += 256) hb[i] = 0.f;

    if (tid >= 192) {
        int f = tid - 192;
        for (int i = f; i < 768; i += 64) {
            int b = i / 96, pos = i - b*96;
            gx_s[b*100 + pos] =
                g_gx[((long)(b0+b)*256 + 0)*768 + (pos>>5)*256 + co + (pos&31)];
        }
    }

    int ub = tid >> 5, uc = tid & 31;
    uint32_t local_addr = s2u(hb) + (uint32_t)((ub*256 + co + uc) * 4);
    uint32_t radr[8];
    #pragma unroll
    for (int r = 0; r < 8; r++) radr[r] = mapa_u32(local_addr, r);
    float h_old = 0.f;
    float* cptr = g_c + ((long)(b0+ub)*256)*256 + co + uc;

    int g = tid >> 1, bbase = (tid & 1) * 4;
    __syncthreads();

    for (int t = 0; t < 256; t++) {
        int p = t & 1, pn = p ^ 1;
        const float* hcur = hb + p*2048;

        if (tid < 192) {
            const float* wr = W_s + g*260;
            const float* h0 = hcur + (bbase+0)*256;
            const float* h1 = hcur + (bbase+1)*256;
            const float* h2 = hcur + (bbase+2)*256;
            const float* h3 = hcur + (bbase+3)*256;
            unsigned long long a0=0ULL, a1=0ULL, a2=0ULL, a3=0ULL;
            #pragma unroll 4
            for (int k = 0; k < 64; k++) {
                ulonglong2 w = *(const ulonglong2*)(wr + k*4);
                ulonglong2 x;
                x = *(const ulonglong2*)(h0 + k*4); FMA2(a0, w.x, x.x); FMA2(a0, w.y, x.y);
                x = *(const ulonglong2*)(h1 + k*4); FMA2(a1, w.x, x.x); FMA2(a1, w.y, x.y);
                x = *(const ulonglong2*)(h2 + k*4); FMA2(a2, w.x, x.x); FMA2(a2, w.y, x.y);
                x = *(const ulonglong2*)(h3 + k*4); FMA2(a3, w.x, x.x); FMA2(a3, w.y, x.y);
            }
            gh_s[g*9 + bbase+0] = pairsum(a0);
            gh_s[g*9 + bbase+1] = pairsum(a1);
            gh_s[g*9 + bbase+2] = pairsum(a2);
            gh_s[g*9 + bbase+3] = pairsum(a3);
        } else if (t < 255) {
            int f = tid - 192;
            float* dst = gx_s + pn*800;
            for (int i = f; i < 768; i += 64) {
                int b = i / 96, pos = i - b*96;
                dst[b*100 + pos] =
                    g_gx[((long)(b0+b)*256 + (t+1))*768 + (pos>>5)*256 + co + (pos&31)];
            }
        }
        __syncthreads();

        {
            const float* gxb = gx_s + p*800 + ub*100;
            float xr = gxb[uc], xz = gxb[32+uc], xn = gxb[64+uc];
            float hr = gh_s[uc*9 + ub]        + bh_s[uc];
            float hz = gh_s[(32+uc)*9 + ub]   + bh_s[32+uc];
            float hn = gh_s[(64+uc)*9 + ub]   + bh_s[64+uc];
            float rg = 1.f / (1.f + expf(-(xr + hr)));
            float zg = 1.f / (1.f + expf(-(xz + hz)));
            float ng = tanhf(xn + rg*hn);
            float hnew = (1.f - zg)*ng + zg*h_old;
            h_old = hnew;
            uint32_t off = (uint32_t)(pn * 8192);
            #pragma unroll
            for (int r = 0; r < 8; r++) st_cluster_f32(radr[r] + off, hnew);
            cptr[t*256] = hnew;
        }
        asm volatile("barrier.cluster.arrive.aligned;" ::: "memory");
        asm volatile("barrier.cluster.wait.aligned;"   ::: "memory");
    }
}

// ---------------- final reduction ---------------------------------------
__global__ void final_kernel(float* __restrict__ out)
{
    __shared__ float sl[256], sa[256];
    int tid = threadIdx.x;
    float L = 0.f, A = 0.f;
    for (int i = tid; i < 6144; i += 256) { L += g_part[i*2]; A += g_part[i*2+1]; }
    sl[tid] = L; sa[tid] = A;
    __syncthreads();
    for (int o = 128; o; o >>= 1) {
        if (tid < o) { sl[tid] += sl[tid+o]; sa[tid] += sa[tid+o]; }
        __syncthreads();
    }
    if (tid == 0) {
        out[0] = sl[0] / (float)NROWS_L;
        out[1] = sa[0] / (float)NROWS_L * 100.f;
    }
}

// ---------------- copy z and c into d_out (8B-aligned dst) ---------------
__global__ void copyout_kernel(float* __restrict__ out)
{
    long i = (long)blockIdx.x * 256 + threadIdx.x;
    float2* dst = (float2*)(out + 2);
    const long NZ2 = 2097152;
    const long NC2 = 4194304;
    if (i < NZ2) {
        dst[i] = ((const float2*)g_z)[i];
    } else if (i < NZ2 + NC2) {
        dst[i] = ((const float2*)g_c)[i - NZ2];
    }
}

// ---------------- host launcher ------------------------------------------
extern "C" void kernel_launch(void* const* d_in, const int* in_sizes, int n_in,
                              void* d_out, int out_size)
{
    const float* rr  = (const float*)d_in[0];
    const float* w1  = (const float*)d_in[1];
    const float* b1  = (const float*)d_in[2];
    const float* w2  = (const float*)d_in[3];
    const float* b2  = (const float*)d_in[4];
    const float* Wih = (const float*)d_in[5];
    const float* Whh = (const float*)d_in[6];
    const float* bih = (const float*)d_in[7];
    const float* bhh = (const float*)d_in[8];
    const float* Wkw = (const float*)d_in[9];
    const float* Wkb = (const float*)d_in[10];

    float* out = (float*)d_out;

    float *pz, *pc, *ph1, *pgx, *pU, *pw1T, *pw2T, *pWkT;
    cudaGetSymbolAddress((void**)&pz,   g_z);
    cudaGetSymbolAddress((void**)&pc,   g_c);
    cudaGetSymbolAddress((void**)&ph1,  g_h1);
    cudaGetSymbolAddress((void**)&pgx,  g_gx);
    cudaGetSymbolAddress((void**)&pU,   g_U);
    cudaGetSymbolAddress((void**)&pw1T, g_w1T);
    cudaGetSymbolAddress((void**)&pw2T, g_w2T);
    cudaGetSymbolAddress((void**)&pWkT, g_WkT);

    cudaFuncSetAttribute(logits_mma,  cudaFuncAttributeMaxDynamicSharedMemorySize, LOG_SMEM);
    cudaFuncSetAttribute(gru_cluster, cudaFuncAttributeMaxDynamicSharedMemorySize, GRU_SMEM);
    cudaFuncSetAttribute(mma_gemm,    cudaFuncAttributeMaxDynamicSharedMemorySize, GEMM_SMEM);

    // 0. weight transposes
    prep_transpose<<<1536, 256>>>(w1, w2, Wkw);
    // 1. encoder layer 1 (relu)
    mma_gemm<<<dim3(2, 256, 1), 256, GEMM_SMEM>>>(
        rr, pw1T, b1, ph1, N_BT, 256, 256, 1, 0, 0, 0, 0);
    // 2. encoder layer 2 -> normalized z (mode 2)
    mma_gemm<<<dim3(1, 256, 1), 256, GEMM_SMEM>>>(
        ph1, pw2T, b2, pz, N_BT, 128, 256, 0, 2, 0, 0, 0);
    // 3. gx = z @ W_ih^T + b_ih
    mma_gemm<<<dim3(6, 256, 1), 256, GEMM_SMEM>>>(
        pz, Wih, bih, pgx, N_BT, 768, 128, 0, 0, 0, 0, 0);
    // 4. GRU (clustered, weight-stationary)
    gru_cluster<<<128, 256, GRU_SMEM>>>(Whh, bhh);
    // 5. U[k] = rowscale10(c @ Wk_w[k] + Wk_b[k])  (mode 1)
    mma_gemm<<<dim3(1, 256, 12), 256, GEMM_SMEM>>>(
        pc, pWkT, Wkb, pU, N_BT, 128, 256, 0, 1,
        32768L, 128L, (long)N_BT * 128);
    // 6. fused logits + reductions (tensor-core)
    logits_mma<<<dim3(4, 128, 12), 256, LOG_SMEM>>>();
    // 7. final loss/accuracy
    final_kernel<<<1, 256>>>(out);
    // 8. copy z_seq and c_seq into d_out
    copyout_kernel<<<24576, 256>>>(out);
}

// round 8
// speedup vs baseline: 1.4877x; 1.1279x over previous
#include <cuda_runtime.h>
#include <math.h>
#include <stdint.h>

// B=128, T=256, W=256, D=128, C=256, K=12, Tp=244, TEMP=0.1
#define N_BT     32768
#define TP       244
#define NROWS_L  374784
// gemm smem: 2 buf x 4 arrays x 128x36 words + 128 bias
#define GEMM_SMEM ((2*4*4608 + 128)*4)
// logits smem: 2 buf x (Uh,Ul 64x36 + Zh,Zl 256x36) + red 3x256 + pad
#define LOG_BUF   (2*2304 + 2*9216)
#define LOG_SMEM  ((2*LOG_BUF + 3*256 + 64)*4)
// GRU2 smem: W 96x260 + hb 2x8x260 + bh 96 (words)
#define GRU2_SMEM ((96*260 + 2*8*260 + 96)*4)

// ---------------- packed f32x2 helpers (GRU) -----------------------------
#define FMA2(d,a,b) asm("fma.rn.f32x2 %0, %1, %2, %0;" : "+l"(d) : "l"(a), "l"(b))
__device__ __forceinline__ void unpack2(unsigned long long v, float& lo, float& hi) {
    asm("mov.b64 {%0, %1}, %2;" : "=f"(lo), "=f"(hi) : "l"(v));
}
__device__ __forceinline__ float pairsum(unsigned long long v) {
    float a, b; unpack2(v, a, b); return a + b;
}
__device__ __forceinline__ uint32_t s2u(const void* p) {
    uint32_t a; asm("{ .reg .u64 t; cvta.to.shared.u64 t, %1; cvt.u32.u64 %0, t; }" : "=r"(a) : "l"(p));
    return a;
}
__device__ __forceinline__ uint32_t mapa_u32(uint32_t addr, uint32_t rank) {
    uint32_t r; asm("mapa.shared::cluster.u32 %0, %1, %2;" : "=r"(r) : "r"(addr), "r"(rank));
    return r;
}
__device__ __forceinline__ void st_cluster_f32(uint32_t addr, float v) {
    asm volatile("st.shared::cluster.f32 [%0], %1;" :: "r"(addr), "f"(v) : "memory");
}
// fast activations (MUFU-based; safe at extremes)
__device__ __forceinline__ float fsig(float x)  { return 1.f / (1.f + __expf(-x)); }
__device__ __forceinline__ float ftanh(float x) { return 1.f - 2.f / (1.f + __expf(2.f*x)); }

// ---------------- tf32 mma helpers ---------------------------------------
__device__ __forceinline__ uint32_t f2tf(float x) {
    uint32_t r; asm("cvt.rna.tf32.f32 %0, %1;" : "=r"(r) : "f"(x)); return r;
}
__device__ __forceinline__ void cvt_hl(float4 x, uint4& h, uint4& l) {
    h.x = f2tf(x.x); l.x = f2tf(x.x - __uint_as_float(h.x));
    h.y = f2tf(x.y); l.y = f2tf(x.y - __uint_as_float(h.y));
    h.z = f2tf(x.z); l.z = f2tf(x.z - __uint_as_float(h.z));
    h.w = f2tf(x.w); l.w = f2tf(x.w - __uint_as_float(h.w));
}
__device__ __forceinline__ void mma8(float* c, const uint32_t* a, const uint32_t* b) {
    asm volatile("mma.sync.aligned.m16n8k8.row.col.f32.tf32.tf32.f32 "
        "{%0,%1,%2,%3}, {%4,%5,%6,%7}, {%8,%9}, {%0,%1,%2,%3};"
        : "+f"(c[0]), "+f"(c[1]), "+f"(c[2]), "+f"(c[3])
        : "r"(a[0]), "r"(a[1]), "r"(a[2]), "r"(a[3]), "r"(b[0]), "r"(b[1]));
}

// ---------------- scratch ------------------------------------------------
__device__ __align__(16) float g_z   [4194304];   // [32768,128] normalized z
__device__ __align__(16) float g_c   [8388608];   // [32768,256] c_seq
__device__ __align__(16) float g_h1  [8388608];   // [32768,256]
__device__ __align__(16) float g_gx  [25165824];  // [32768,768]
__device__ __align__(16) float g_U   [50331648];  // [12,32768,128] rows scaled by 10/||.||
__device__ __align__(16) float g_w1T [65536];
__device__ __align__(16) float g_w2T [32768];
__device__ __align__(16) float g_WkT [393216];
__device__ __align__(16) float g_part[12288];

// ---------------- prep: transposes --------------------------------------
__global__ void prep_transpose(const float* __restrict__ w1, const float* __restrict__ w2,
                               const float* __restrict__ wk)
{
    long i = (long)blockIdx.x * 256 + threadIdx.x;
    if (i < 65536) {
        int n = (int)(i >> 8), k = (int)(i & 255);
        g_w1T[n*256 + k] = w1[k*256 + n];
    }
    if (i < 32768) {
        int n = (int)(i >> 8), k = (int)(i & 255);
        g_w2T[n*256 + k] = w2[k*128 + n];
    }
    if (i < 393216) {
        long kk = i / 32768; long r = i % 32768;
        int d = (int)(r >> 8), c = (int)(r & 255);
        g_WkT[kk*32768 + d*256 + c] = wk[kk*32768 + c*128 + d];
    }
}

// ---------------- 3xTF32 mma.sync NT-GEMM (hi/lo staged in smem) ---------
__global__ __launch_bounds__(256, 1) void mma_gemm(
    const float* __restrict__ A, const float* __restrict__ Bm,
    const float* __restrict__ bias, float* __restrict__ Cm,
    int M, int N, int K, int relu, int mode,
    long sB, long sBias, long sC)
{
    extern __shared__ uint32_t smu[];
    float* sbias = (float*)(smu + 36864);
    float* rs    = (float*)smu;          // overlay [128][17]
    float* rinv  = (float*)(smu + 2176);

    const float* Bz = Bm  + (long)blockIdx.z * sB;
    const float* bz = bias + (long)blockIdx.z * sBias;
    float*       Cz = Cm  + (long)blockIdx.z * sC;
    int m0 = blockIdx.y * 128, n0 = blockIdx.x * 128;

    int tid = threadIdx.x;
    int wid = tid >> 5, lane = tid & 31;
    int wm = wid >> 2, wn = wid & 3;
    int gid = lane >> 2, tig = lane & 3;

    if (tid < 128) sbias[tid] = bz[n0 + tid];

    const float* Ag = A  + (long)m0 * K;
    const float* Bg = Bz + (long)n0 * K;

    float c[4][4][4];
    #pragma unroll
    for (int i = 0; i < 4; i++)
        #pragma unroll
        for (int j = 0; j < 4; j++)
            #pragma unroll
            for (int q = 0; q < 4; q++) c[i][j][q] = 0.f;

    float4 ra[4], rb[4];
    #pragma unroll
    for (int l = 0; l < 4; l++) {
        int u = tid + l*256, r = u >> 3, c4 = u & 7;
        ra[l] = *(const float4*)(Ag + (long)r*K + c4*4);
        rb[l] = *(const float4*)(Bg + (long)r*K + c4*4);
    }
    #pragma unroll
    for (int l = 0; l < 4; l++) {
        int u = tid + l*256, r = u >> 3, c4 = u & 7;
        uint4 h, lo;
        cvt_hl(ra[l], h, lo);
        *(uint4*)(smu + 0    + r*36 + c4*4) = h;
        *(uint4*)(smu + 4608 + r*36 + c4*4) = lo;
        cvt_hl(rb[l], h, lo);
        *(uint4*)(smu + 9216  + r*36 + c4*4) = h;
        *(uint4*)(smu + 13824 + r*36 + c4*4) = lo;
    }
    __syncthreads();

    int NC = K >> 5;
    for (int kc = 0; kc < NC; kc++) {
        const uint32_t* base = smu + (kc & 1)*18432;
        bool nxt = (kc + 1 < NC);
        if (nxt) {
            int k0 = (kc + 1) * 32;
            #pragma unroll
            for (int l = 0; l < 4; l++) {
                int u = tid + l*256, r = u >> 3, c4 = u & 7;
                ra[l] = *(const float4*)(Ag + (long)r*K + k0 + c4*4);
                rb[l] = *(const float4*)(Bg + (long)r*K + k0 + c4*4);
            }
        }
        #pragma unroll
        for (int ks = 0; ks < 4; ks++) {
            int k = ks * 8;
            uint32_t ah[4][4], al[4][4];
            #pragma unroll
            for (int i = 0; i < 4; i++) {
                int r0 = wm*64 + i*16 + gid;
                ah[i][0] = base[r0*36 + k + tig];
                ah[i][1] = base[(r0+8)*36 + k + tig];
                ah[i][2] = base[r0*36 + k + tig + 4];
                ah[i][3] = base[(r0+8)*36 + k + tig + 4];
                al[i][0] = base[4608 + r0*36 + k + tig];
                al[i][1] = base[4608 + (r0+8)*36 + k + tig];
                al[i][2] = base[4608 + r0*36 + k + tig + 4];
                al[i][3] = base[4608 + (r0+8)*36 + k + tig + 4];
            }
            #pragma unroll
            for (int j = 0; j < 4; j++) {
                int n = wn*32 + j*8 + gid;
                uint32_t bh[2], bl[2];
                bh[0] = base[9216 + n*36 + k + tig];
                bh[1] = base[9216 + n*36 + k + tig + 4];
                bl[0] = base[13824 + n*36 + k + tig];
                bl[1] = base[13824 + n*36 + k + tig + 4];
                #pragma unroll
                for (int i = 0; i < 4; i++) {
                    mma8(c[i][j], ah[i], bh);
                    mma8(c[i][j], ah[i], bl);
                    mma8(c[i][j], al[i], bh);
                }
            }
        }
        if (nxt) {
            uint32_t* nb = smu + ((kc + 1) & 1)*18432;
            #pragma unroll
            for (int l = 0; l < 4; l++) {
                int u = tid + l*256, r = u >> 3, c4 = u & 7;
                uint4 h, lo;
                cvt_hl(ra[l], h, lo);
                *(uint4*)(nb + 0    + r*36 + c4*4) = h;
                *(uint4*)(nb + 4608 + r*36 + c4*4) = lo;
                cvt_hl(rb[l], h, lo);
                *(uint4*)(nb + 9216  + r*36 + c4*4) = h;
                *(uint4*)(nb + 13824 + r*36 + c4*4) = lo;
            }
            __syncthreads();
        }
    }

    #pragma unroll
    for (int i = 0; i < 4; i++)
        #pragma unroll
        for (int j = 0; j < 4; j++) {
            int colb = wn*32 + j*8 + tig*2;
            c[i][j][0] += sbias[colb]; c[i][j][1] += sbias[colb+1];
            c[i][j][2] += sbias[colb]; c[i][j][3] += sbias[colb+1];
        }

    if (mode == 0) {
        #pragma unroll
        for (int i = 0; i < 4; i++) {
            int r0 = m0 + wm*64 + i*16 + gid;
            #pragma unroll
            for (int j = 0; j < 4; j++) {
                int colb = n0 + wn*32 + j*8 + tig*2;
                float2 v0 = make_float2(c[i][j][0], c[i][j][1]);
                float2 v1 = make_float2(c[i][j][2], c[i][j][3]);
                if (relu) {
                    v0.x = fmaxf(v0.x, 0.f); v0.y = fmaxf(v0.y, 0.f);
                    v1.x = fmaxf(v1.x, 0.f); v1.y = fmaxf(v1.y, 0.f);
                }
                *(float2*)(Cz + (long)r0*N + colb)     = v0;
                *(float2*)(Cz + (long)(r0+8)*N + colb) = v1;
            }
        }
    } else {
        __syncthreads();
        #pragma unroll
        for (int i = 0; i < 4; i++) {
            float ss0 = 0.f, ss1 = 0.f;
            #pragma unroll
            for (int j = 0; j < 4; j++) {
                ss0 += c[i][j][0]*c[i][j][0] + c[i][j][1]*c[i][j][1];
                ss1 += c[i][j][2]*c[i][j][2] + c[i][j][3]*c[i][j][3];
            }
            int r0 = wm*64 + i*16 + gid;
            rs[r0*17 + wn*4 + tig]     = ss0;
            rs[(r0+8)*17 + wn*4 + tig] = ss1;
        }
        __syncthreads();
        if (tid < 128) {
            float ss = 0.f;
            #pragma unroll
            for (int x = 0; x < 16; x++) ss += rs[tid*17 + x];
            float inv = 1.f / fmaxf(sqrtf(ss), 1e-12f);
            if (mode == 1) inv *= 10.f;
            rinv[tid] = inv;
        }
        __syncthreads();
        #pragma unroll
        for (int i = 0; i < 4; i++) {
            int rr = wm*64 + i*16 + gid;
            float sc0 = rinv[rr], sc1 = rinv[rr+8];
            int r0 = m0 + rr;
            #pragma unroll
            for (int j = 0; j < 4; j++) {
                int colb = n0 + wn*32 + j*8 + tig*2;
                *(float2*)(Cz + (long)r0*N + colb) =
                    make_float2(c[i][j][0]*sc0, c[i][j][1]*sc0);
                *(float2*)(Cz + (long)(r0+8)*N + colb) =
                    make_float2(c[i][j][2]*sc1, c[i][j][3]*sc1);
            }
        }
    }
}

// ---------------- logits via 3xTF32 mma + fused reductions ---------------
__global__ __launch_bounds__(256, 1) void logits_mma()
{
    extern __shared__ uint32_t smu[];
    float* redL = (float*)(smu + 2*LOG_BUF);
    float* redM = redL + 256;
    float* redP = redM + 256;
    float* wred = redP + 256;

    int tile = blockIdx.x, b = blockIdx.y, kk = blockIdx.z;
    int t0 = tile * 64;
    int tid = threadIdx.x;
    int wid = tid >> 5, lane = tid & 31;
    int wm = wid >> 2, wn = wid & 3;
    int gid = lane >> 2, tig = lane & 3;

    const float* Ug = g_U + ((long)kk*32768 + (long)b*256 + t0) * 128;
    const float* Zg = g_z + (long)b * 32768;

    float c[2][8][4];
    #pragma unroll
    for (int i = 0; i < 2; i++)
        #pragma unroll
        for (int j = 0; j < 8; j++)
            #pragma unroll
            for (int q = 0; q < 4; q++) c[i][j][q] = 0.f;

    float4 rz[8], ru[2];
    #pragma unroll
    for (int l = 0; l < 8; l++) {
        int u = tid + l*256, r = u >> 3, c4 = u & 7;
        rz[l] = *(const float4*)(Zg + (long)r*128 + c4*4);
    }
    #pragma unroll
    for (int l = 0; l < 2; l++) {
        int u = tid + l*256, r = u >> 3, c4 = u & 7;
        ru[l] = *(const float4*)(Ug + (long)r*128 + c4*4);
    }
    #pragma unroll
    for (int l = 0; l < 8; l++) {
        int u = tid + l*256, r = u >> 3, c4 = u & 7;
        uint4 h, lo; cvt_hl(rz[l], h, lo);
        *(uint4*)(smu + 4608  + r*36 + c4*4) = h;
        *(uint4*)(smu + 13824 + r*36 + c4*4) = lo;
    }
    #pragma unroll
    for (int l = 0; l < 2; l++) {
        int u = tid + l*256, r = u >> 3, c4 = u & 7;
        uint4 h, lo; cvt_hl(ru[l], h, lo);
        *(uint4*)(smu + 0    + r*36 + c4*4) = h;
        *(uint4*)(smu + 2304 + r*36 + c4*4) = lo;
    }
    __syncthreads();

    #pragma unroll
    for (int kc = 0; kc < 4; kc++) {
        const uint32_t* base = smu + (kc & 1)*LOG_BUF;
        bool nxt = (kc < 3);
        if (nxt) {
            int k0 = (kc + 1) * 32;
            #pragma unroll
            for (int l = 0; l < 8; l++) {
                int u = tid + l*256, r = u >> 3, c4 = u & 7;
                rz[l] = *(const float4*)(Zg + (long)r*128 + k0 + c4*4);
            }
            #pragma unroll
            for (int l = 0; l < 2; l++) {
                int u = tid + l*256, r = u >> 3, c4 = u & 7;
                ru[l] = *(const float4*)(Ug + (long)r*128 + k0 + c4*4);
            }
        }
        #pragma unroll
        for (int ks = 0; ks < 4; ks++) {
            int k = ks * 8;
            uint32_t ah[2][4], al[2][4];
            #pragma unroll
            for (int i = 0; i < 2; i++) {
                int r0 = wm*32 + i*16 + gid;
                ah[i][0] = base[r0*36 + k + tig];
                ah[i][1] = base[(r0+8)*36 + k + tig];
                ah[i][2] = base[r0*36 + k + tig + 4];
                ah[i][3] = base[(r0+8)*36 + k + tig + 4];
                al[i][0] = base[2304 + r0*36 + k + tig];
                al[i][1] = base[2304 + (r0+8)*36 + k + tig];
                al[i][2] = base[2304 + r0*36 + k + tig + 4];
                al[i][3] = base[2304 + (r0+8)*36 + k + tig + 4];
            }
            #pragma unroll
            for (int j = 0; j < 8; j++) {
                int n = wn*64 + j*8 + gid;
                uint32_t bh[2], bl[2];
                bh[0] = base[4608 + n*36 + k + tig];
                bh[1] = base[4608 + n*36 + k + tig + 4];
                bl[0] = base[13824 + n*36 + k + tig];
                bl[1] = base[13824 + n*36 + k + tig + 4];
                #pragma unroll
                for (int i = 0; i < 2; i++) {
                    mma8(c[i][j], ah[i], bh);
                    mma8(c[i][j], ah[i], bl);
                    mma8(c[i][j], al[i], bh);
                }
            }
        }
        if (nxt) {
            uint32_t* nb = smu + ((kc + 1) & 1)*LOG_BUF;
            #pragma unroll
            for (int l = 0; l < 8; l++) {
                int u = tid + l*256, r = u >> 3, c4 = u & 7;
                uint4 h, lo; cvt_hl(rz[l], h, lo);
                *(uint4*)(nb + 4608  + r*36 + c4*4) = h;
                *(uint4*)(nb + 13824 + r*36 + c4*4) = lo;
            }
            #pragma unroll
            for (int l = 0; l < 2; l++) {
                int u = tid + l*256, r = u >> 3, c4 = u & 7;
                uint4 h, lo; cvt_hl(ru[l], h, lo);
                *(uint4*)(nb + 0    + r*36 + c4*4) = h;
                *(uint4*)(nb + 2304 + r*36 + c4*4) = lo;
            }
            __syncthreads();
        }
    }

    #pragma unroll
    for (int i = 0; i < 2; i++) {
        #pragma unroll
        for (int sub = 0; sub < 2; sub++) {
            int rrow = wm*32 + i*16 + sub*8 + gid;
            int spos = t0 + rrow + kk + 1;
            float lsum = 0.f, nmax = -3.0e38f, pos = -3.0e38f;
            #pragma unroll
            for (int j = 0; j < 8; j++) {
                #pragma unroll
                for (int p = 0; p < 2; p++) {
                    int col = wn*64 + j*8 + tig*2 + p;
                    float l = c[i][j][sub*2 + p];
                    lsum += __expf(l);
                    if (col == spos) pos = l;
                    else             nmax = fmaxf(nmax, l);
                }
            }
            #pragma unroll
            for (int o = 1; o <= 2; o <<= 1) {
                lsum += __shfl_xor_sync(0xffffffffu, lsum, o);
                nmax = fmaxf(nmax, __shfl_xor_sync(0xffffffffu, nmax, o));
                pos  = fmaxf(pos,  __shfl_xor_sync(0xffffffffu, pos,  o));
            }
            if (tig == 0) {
                redL[wn*64 + rrow] = lsum;
                redM[wn*64 + rrow] = nmax;
                redP[wn*64 + rrow] = pos;
            }
        }
    }
    __syncthreads();

    float loss_tot = 0.f, acc_tot = 0.f;
    if (tid < 64) {
        float ls = redL[tid] + redL[64+tid] + redL[128+tid] + redL[192+tid];
        float nm = fmaxf(fmaxf(redM[tid], redM[64+tid]), fmaxf(redM[128+tid], redM[192+tid]));
        float ps = fmaxf(fmaxf(redP[tid], redP[64+tid]), fmaxf(redP[128+tid], redP[192+tid]));
        int t = t0 + tid;
        if (t < TP) {
            loss_tot = logf(ls) - ps;
            acc_tot  = (ps >= nm) ? 1.f : 0.f;
        }
    }
    if (wid < 2) {
        #pragma unroll
        for (int o = 16; o; o >>= 1) {
            loss_tot += __shfl_xor_sync(0xffffffffu, loss_tot, o);
            acc_tot  += __shfl_xor_sync(0xffffffffu, acc_tot,  o);
        }
        if (lane == 0) { wred[wid*2] = loss_tot; wred[wid*2+1] = acc_tot; }
    }
    __syncthreads();
    if (tid == 0) {
        long bid = ((long)kk*128 + b)*4 + tile;
        g_part[bid*2]   = wred[0] + wred[2];
        g_part[bid*2+1] = wred[1] + wred[3];
    }
}

// ---------------- GRU v2: (channel,batch) threads, no per-step sync ------
// 16 clusters x 8 CTAs. CTA rank owns channels [32r,32r+32): W rows
// {c, 256+c, 512+c}+co in SMEM (stationary). Thread (c,b) computes all 3
// gates for its pair; gx via 3 direct LDGs hidden under the GEMV.
__global__ __launch_bounds__(256, 1) __cluster_dims__(8, 1, 1)
void gru2(const float* __restrict__ Whh, const float* __restrict__ bhh)
{
    extern __shared__ float s[];
    float* W_s  = s;                       // [96][260]  (row q*32+c)
    float* hb   = s + 96*260;              // [2][8][260]
    float* bh_s = hb + 2*8*260;            // [96]

    int tid  = threadIdx.x;
    int rank = blockIdx.x & 7;
    int cl   = blockIdx.x >> 3;
    int co   = rank * 32;
    int b0   = cl * 8;

    // load W rows: local row r = q*32+c -> global row q*256 + co + c
    for (int i = tid; i < 96*256; i += 256) {
        int r = i >> 8, k = i & 255;
        int grow = (r >> 5)*256 + co + (r & 31);
        W_s[r*260 + k] = Whh[grow*256 + k];
    }
    if (tid < 96) {
        int grow = (tid >> 5)*256 + co + (tid & 31);
        bh_s[tid] = bhh[grow];
    }
    for (int i = tid; i < 2*8*260; i += 256) hb[i] = 0.f;

    int c = tid >> 3, b = tid & 7;
    const float* gxp = g_gx + ((long)(b0+b) * 256) * 768 + co + c;
    float*       cp  = g_c  + ((long)(b0+b) * 256) * 256 + co + c;
    uint32_t ladr = s2u(hb) + (uint32_t)((b*260 + co + c) * 4);
    uint32_t radr[8];
    #pragma unroll
    for (int r = 0; r < 8; r++) radr[r] = mapa_u32(ladr, r);

    const float* w0 = W_s + c*260;
    const float* w1 = W_s + (32 + c)*260;
    const float* w2 = W_s + (64 + c)*260;
    float h_old = 0.f;

    __syncthreads();
    asm volatile("barrier.cluster.arrive.aligned;" ::: "memory");
    asm volatile("barrier.cluster.wait.aligned;"   ::: "memory");

    for (int t = 0; t < 256; t++) {
        int p = t & 1, pn = p ^ 1;
        // gx loads (latency hidden by GEMV below)
        float xr = gxp[(long)t*768];
        float xz = gxp[(long)t*768 + 256];
        float xn = gxp[(long)t*768 + 512];

        const float* hp = hb + p*2080 + b*260;
        unsigned long long a0 = 0ULL, a1 = 0ULL, a2 = 0ULL;
        #pragma unroll 16
        for (int k4 = 0; k4 < 64; k4++) {
            ulonglong2 h4 = *(const ulonglong2*)(hp + k4*4);
            ulonglong2 v0 = *(const ulonglong2*)(w0 + k4*4);
            ulonglong2 v1 = *(const ulonglong2*)(w1 + k4*4);
            ulonglong2 v2 = *(const ulonglong2*)(w2 + k4*4);
            FMA2(a0, v0.x, h4.x); FMA2(a0, v0.y, h4.y);
            FMA2(a1, v1.x, h4.x); FMA2(a1, v1.y, h4.y);
            FMA2(a2, v2.x, h4.x); FMA2(a2, v2.y, h4.y);
        }
        float hr = pairsum(a0) + bh_s[c];
        float hz = pairsum(a1) + bh_s[32 + c];
        float hn = pairsum(a2) + bh_s[64 + c];

        float rg = fsig(xr + hr);
        float zg = fsig(xz + hz);
        float ng = ftanh(xn + rg*hn);
        float hnew = (1.f - zg)*ng + zg*h_old;
        h_old = hnew;

        uint32_t off = (uint32_t)(pn * 8320);   // 2080 floats
        #pragma unroll
        for (int r = 0; r < 8; r++) st_cluster_f32(radr[r] + off, hnew);
        cp[(long)t*256] = hnew;

        asm volatile("barrier.cluster.arrive.aligned;" ::: "memory");
        asm volatile("barrier.cluster.wait.aligned;"   ::: "memory");
    }
}

// ---------------- final reduction ---------------------------------------
__global__ void final_kernel(float* __restrict__ out)
{
    __shared__ float sl[256], sa[256];
    int tid = threadIdx.x;
    float L = 0.f, A = 0.f;
    for (int i = tid; i < 6144; i += 256) { L += g_part[i*2]; A += g_part[i*2+1]; }
    sl[tid] = L; sa[tid] = A;
    __syncthreads();
    for (int o = 128; o; o >>= 1) {
        if (tid < o) { sl[tid] += sl[tid+o]; sa[tid] += sa[tid+o]; }
        __syncthreads();
    }
    if (tid == 0) {
        out[0] = sl[0] / (float)NROWS_L;
        out[1] = sa[0] / (float)NROWS_L * 100.f;
    }
}

// ---------------- copy z and c into d_out (8B-aligned dst) ---------------
__global__ void copyout_kernel(float* __restrict__ out)
{
    long i = (long)blockIdx.x * 256 + threadIdx.x;
    float2* dst = (float2*)(out + 2);
    const long NZ2 = 2097152;
    const long NC2 = 4194304;
    if (i < NZ2) {
        dst[i] = ((const float2*)g_z)[i];
    } else if (i < NZ2 + NC2) {
        dst[i] = ((const float2*)g_c)[i - NZ2];
    }
}

// ---------------- host launcher ------------------------------------------
extern "C" void kernel_launch(void* const* d_in, const int* in_sizes, int n_in,
                              void* d_out, int out_size)
{
    const float* rr  = (const float*)d_in[0];
    const float* w1  = (const float*)d_in[1];
    const float* b1  = (const float*)d_in[2];
    const float* w2  = (const float*)d_in[3];
    const float* b2  = (const float*)d_in[4];
    const float* Wih = (const float*)d_in[5];
    const float* Whh = (const float*)d_in[6];
    const float* bih = (const float*)d_in[7];
    const float* bhh = (const float*)d_in[8];
    const float* Wkw = (const float*)d_in[9];
    const float* Wkb = (const float*)d_in[10];

    float* out = (float*)d_out;

    float *pz, *pc, *ph1, *pgx, *pU, *pw1T, *pw2T, *pWkT;
    cudaGetSymbolAddress((void**)&pz,   g_z);
    cudaGetSymbolAddress((void**)&pc,   g_c);
    cudaGetSymbolAddress((void**)&ph1,  g_h1);
    cudaGetSymbolAddress((void**)&pgx,  g_gx);
    cudaGetSymbolAddress((void**)&pU,   g_U);
    cudaGetSymbolAddress((void**)&pw1T, g_w1T);
    cudaGetSymbolAddress((void**)&pw2T, g_w2T);
    cudaGetSymbolAddress((void**)&pWkT, g_WkT);

    cudaFuncSetAttribute(logits_mma, cudaFuncAttributeMaxDynamicSharedMemorySize, LOG_SMEM);
    cudaFuncSetAttribute(gru2,       cudaFuncAttributeMaxDynamicSharedMemorySize, GRU2_SMEM);
    cudaFuncSetAttribute(mma_gemm,   cudaFuncAttributeMaxDynamicSharedMemorySize, GEMM_SMEM);

    // 0. weight transposes
    prep_transpose<<<1536, 256>>>(w1, w2, Wkw);
    // 1. encoder layer 1 (relu)
    mma_gemm<<<dim3(2, 256, 1), 256, GEMM_SMEM>>>(
        rr, pw1T, b1, ph1, N_BT, 256, 256, 1, 0, 0, 0, 0);
    // 2. encoder layer 2 -> normalized z (mode 2)
    mma_gemm<<<dim3(1, 256, 1), 256, GEMM_SMEM>>>(
        ph1, pw2T, b2, pz, N_BT, 128, 256, 0, 2, 0, 0, 0);
    // 3. gx = z @ W_ih^T + b_ih
    mma_gemm<<<dim3(6, 256, 1), 256, GEMM_SMEM>>>(
        pz, Wih, bih, pgx, N_BT, 768, 128, 0, 0, 0, 0, 0);
    // 4. GRU v2 (clustered, weight-stationary, syncless steps)
    gru2<<<128, 256, GRU2_SMEM>>>(Whh, bhh);
    // 5. U[k] = rowscale10(c @ Wk_w[k] + Wk_b[k])  (mode 1)
    mma_gemm<<<dim3(1, 256, 12), 256, GEMM_SMEM>>>(
        pc, pWkT, Wkb, pU, N_BT, 128, 256, 0, 1,
        32768L, 128L, (long)N_BT * 128);
    // 6. fused logits + reductions (tensor-core)
    logits_mma<<<dim3(4, 128, 12), 256, LOG_SMEM>>>();
    // 7. final loss/accuracy
    final_kernel<<<1, 256>>>(out);
    // 8. copy z_seq and c_seq into d_out
    copyout_kernel<<<24576, 256>>>(out);
}

// round 9
// speedup vs baseline: 1.8235x; 1.2258x over previous
#include <cuda_runtime.h>
#include <math.h>
#include <stdint.h>

// B=128, T=256, W=256, D=128, C=256, K=12, Tp=244, TEMP=0.1
#define N_BT     32768
#define TP       244
#define NROWS_L  374784
// gemm smem: 2 buf x 4 arrays x 128x36 words + 128 bias
#define GEMM_SMEM ((2*4*4608 + 128)*4)
// logits smem
#define LOG_BUF   (2*2304 + 2*9216)
#define LOG_SMEM  ((2*LOG_BUF + 3*256 + 64)*4)
// GRU3 smem: hb [2][8][264] words
#define GRU3_SMEM (2*8*264*4)

// ---------------- packed f32x2 helpers -----------------------------------
#define FMA2(d,a,b) asm("fma.rn.f32x2 %0, %1, %2, %0;" : "+l"(d) : "l"(a), "l"(b))
__device__ __forceinline__ void unpack2(unsigned long long v, float& lo, float& hi) {
    asm("mov.b64 {%0, %1}, %2;" : "=f"(lo), "=f"(hi) : "l"(v));
}
__device__ __forceinline__ float pairsum(unsigned long long v) {
    float a, b; unpack2(v, a, b); return a + b;
}
__device__ __forceinline__ uint32_t s2u(const void* p) {
    uint32_t a; asm("{ .reg .u64 t; cvta.to.shared.u64 t, %1; cvt.u32.u64 %0, t; }" : "=r"(a) : "l"(p));
    return a;
}
__device__ __forceinline__ uint32_t mapa_u32(uint32_t addr, uint32_t rank) {
    uint32_t r; asm("mapa.shared::cluster.u32 %0, %1, %2;" : "=r"(r) : "r"(addr), "r"(rank));
    return r;
}
__device__ __forceinline__ void st_cluster_f32(uint32_t addr, float v) {
    asm volatile("st.shared::cluster.f32 [%0], %1;" :: "r"(addr), "f"(v) : "memory");
}
__device__ __forceinline__ float fsig(float x)  { return 1.f / (1.f + __expf(-x)); }
__device__ __forceinline__ float ftanh(float x) { return 1.f - 2.f / (1.f + __expf(2.f*x)); }

// ---------------- tf32 mma helpers ---------------------------------------
__device__ __forceinline__ uint32_t f2tf(float x) {
    uint32_t r; asm("cvt.rna.tf32.f32 %0, %1;" : "=r"(r) : "f"(x)); return r;
}
__device__ __forceinline__ void cvt_hl(float4 x, uint4& h, uint4& l) {
    h.x = f2tf(x.x); l.x = f2tf(x.x - __uint_as_float(h.x));
    h.y = f2tf(x.y); l.y = f2tf(x.y - __uint_as_float(h.y));
    h.z = f2tf(x.z); l.z = f2tf(x.z - __uint_as_float(h.z));
    h.w = f2tf(x.w); l.w = f2tf(x.w - __uint_as_float(h.w));
}
__device__ __forceinline__ void mma8(float* c, const uint32_t* a, const uint32_t* b) {
    asm volatile("mma.sync.aligned.m16n8k8.row.col.f32.tf32.tf32.f32 "
        "{%0,%1,%2,%3}, {%4,%5,%6,%7}, {%8,%9}, {%0,%1,%2,%3};"
        : "+f"(c[0]), "+f"(c[1]), "+f"(c[2]), "+f"(c[3])
        : "r"(a[0]), "r"(a[1]), "r"(a[2]), "r"(a[3]), "r"(b[0]), "r"(b[1]));
}

// ---------------- scratch ------------------------------------------------
__device__ __align__(16) float g_z   [4194304];   // [32768,128] normalized z
__device__ __align__(16) float g_c   [8388608];   // [32768,256] c_seq
__device__ __align__(16) float g_h1  [8388608];   // [32768,256]
__device__ __align__(16) float g_gx  [25165824];  // [32768,768]
__device__ __align__(16) float g_U   [50331648];  // [12,32768,128] rows scaled by 10/||.||
__device__ __align__(16) float g_w1T [65536];
__device__ __align__(16) float g_w2T [32768];
__device__ __align__(16) float g_WkT [393216];
__device__ __align__(16) float g_part[12288];

// ---------------- prep: transposes --------------------------------------
__global__ void prep_transpose(const float* __restrict__ w1, const float* __restrict__ w2,
                               const float* __restrict__ wk)
{
    long i = (long)blockIdx.x * 256 + threadIdx.x;
    if (i < 65536) {
        int n = (int)(i >> 8), k = (int)(i & 255);
        g_w1T[n*256 + k] = w1[k*256 + n];
    }
    if (i < 32768) {
        int n = (int)(i >> 8), k = (int)(i & 255);
        g_w2T[n*256 + k] = w2[k*128 + n];
    }
    if (i < 393216) {
        long kk = i / 32768; long r = i % 32768;
        int d = (int)(r >> 8), c = (int)(r & 255);
        g_WkT[kk*32768 + d*256 + c] = wk[kk*32768 + c*128 + d];
    }
}

// ---------------- 3xTF32 mma.sync NT-GEMM (hi/lo staged in smem) ---------
__global__ __launch_bounds__(256, 1) void mma_gemm(
    const float* __restrict__ A, const float* __restrict__ Bm,
    const float* __restrict__ bias, float* __restrict__ Cm,
    int M, int N, int K, int relu, int mode,
    long sB, long sBias, long sC)
{
    extern __shared__ uint32_t smu[];
    float* sbias = (float*)(smu + 36864);
    float* rs    = (float*)smu;          // overlay [128][17]
    float* rinv  = (float*)(smu + 2176);

    const float* Bz = Bm  + (long)blockIdx.z * sB;
    const float* bz = bias + (long)blockIdx.z * sBias;
    float*       Cz = Cm  + (long)blockIdx.z * sC;
    int m0 = blockIdx.y * 128, n0 = blockIdx.x * 128;

    int tid = threadIdx.x;
    int wid = tid >> 5, lane = tid & 31;
    int wm = wid >> 2, wn = wid & 3;
    int gid = lane >> 2, tig = lane & 3;

    if (tid < 128) sbias[tid] = bz[n0 + tid];

    const float* Ag = A  + (long)m0 * K;
    const float* Bg = Bz + (long)n0 * K;

    float c[4][4][4];
    #pragma unroll
    for (int i = 0; i < 4; i++)
        #pragma unroll
        for (int j = 0; j < 4; j++)
            #pragma unroll
            for (int q = 0; q < 4; q++) c[i][j][q] = 0.f;

    float4 ra[4], rb[4];
    #pragma unroll
    for (int l = 0; l < 4; l++) {
        int u = tid + l*256, r = u >> 3, c4 = u & 7;
        ra[l] = *(const float4*)(Ag + (long)r*K + c4*4);
        rb[l] = *(const float4*)(Bg + (long)r*K + c4*4);
    }
    #pragma unroll
    for (int l = 0; l < 4; l++) {
        int u = tid + l*256, r = u >> 3, c4 = u & 7;
        uint4 h, lo;
        cvt_hl(ra[l], h, lo);
        *(uint4*)(smu + 0    + r*36 + c4*4) = h;
        *(uint4*)(smu + 4608 + r*36 + c4*4) = lo;
        cvt_hl(rb[l], h, lo);
        *(uint4*)(smu + 9216  + r*36 + c4*4) = h;
        *(uint4*)(smu + 13824 + r*36 + c4*4) = lo;
    }
    __syncthreads();

    int NC = K >> 5;
    for (int kc = 0; kc < NC; kc++) {
        const uint32_t* base = smu + (kc & 1)*18432;
        bool nxt = (kc + 1 < NC);
        if (nxt) {
            int k0 = (kc + 1) * 32;
            #pragma unroll
            for (int l = 0; l < 4; l++) {
                int u = tid + l*256, r = u >> 3, c4 = u & 7;
                ra[l] = *(const float4*)(Ag + (long)r*K + k0 + c4*4);
                rb[l] = *(const float4*)(Bg + (long)r*K + k0 + c4*4);
            }
        }
        #pragma unroll
        for (int ks = 0; ks < 4; ks++) {
            int k = ks * 8;
            uint32_t ah[4][4], al[4][4];
            #pragma unroll
            for (int i = 0; i < 4; i++) {
                int r0 = wm*64 + i*16 + gid;
                ah[i][0] = base[r0*36 + k + tig];
                ah[i][1] = base[(r0+8)*36 + k + tig];
                ah[i][2] = base[r0*36 + k + tig + 4];
                ah[i][3] = base[(r0+8)*36 + k + tig + 4];
                al[i][0] = base[4608 + r0*36 + k + tig];
                al[i][1] = base[4608 + (r0+8)*36 + k + tig];
                al[i][2] = base[4608 + r0*36 + k + tig + 4];
                al[i][3] = base[4608 + (r0+8)*36 + k + tig + 4];
            }
            #pragma unroll
            for (int j = 0; j < 4; j++) {
                int n = wn*32 + j*8 + gid;
                uint32_t bh[2], bl[2];
                bh[0] = base[9216 + n*36 + k + tig];
                bh[1] = base[9216 + n*36 + k + tig + 4];
                bl[0] = base[13824 + n*36 + k + tig];
                bl[1] = base[13824 + n*36 + k + tig + 4];
                #pragma unroll
                for (int i = 0; i < 4; i++) {
                    mma8(c[i][j], ah[i], bh);
                    mma8(c[i][j], ah[i], bl);
                    mma8(c[i][j], al[i], bh);
                }
            }
        }
        if (nxt) {
            uint32_t* nb = smu + ((kc + 1) & 1)*18432;
            #pragma unroll
            for (int l = 0; l < 4; l++) {
                int u = tid + l*256, r = u >> 3, c4 = u & 7;
                uint4 h, lo;
                cvt_hl(ra[l], h, lo);
                *(uint4*)(nb + 0    + r*36 + c4*4) = h;
                *(uint4*)(nb + 4608 + r*36 + c4*4) = lo;
                cvt_hl(rb[l], h, lo);
                *(uint4*)(nb + 9216  + r*36 + c4*4) = h;
                *(uint4*)(nb + 13824 + r*36 + c4*4) = lo;
            }
            __syncthreads();
        }
    }

    #pragma unroll
    for (int i = 0; i < 4; i++)
        #pragma unroll
        for (int j = 0; j < 4; j++) {
            int colb = wn*32 + j*8 + tig*2;
            c[i][j][0] += sbias[colb]; c[i][j][1] += sbias[colb+1];
            c[i][j][2] += sbias[colb]; c[i][j][3] += sbias[colb+1];
        }

    if (mode == 0) {
        #pragma unroll
        for (int i = 0; i < 4; i++) {
            int r0 = m0 + wm*64 + i*16 + gid;
            #pragma unroll
            for (int j = 0; j < 4; j++) {
                int colb = n0 + wn*32 + j*8 + tig*2;
                float2 v0 = make_float2(c[i][j][0], c[i][j][1]);
                float2 v1 = make_float2(c[i][j][2], c[i][j][3]);
                if (relu) {
                    v0.x = fmaxf(v0.x, 0.f); v0.y = fmaxf(v0.y, 0.f);
                    v1.x = fmaxf(v1.x, 0.f); v1.y = fmaxf(v1.y, 0.f);
                }
                *(float2*)(Cz + (long)r0*N + colb)     = v0;
                *(float2*)(Cz + (long)(r0+8)*N + colb) = v1;
            }
        }
    } else {
        __syncthreads();
        #pragma unroll
        for (int i = 0; i < 4; i++) {
            float ss0 = 0.f, ss1 = 0.f;
            #pragma unroll
            for (int j = 0; j < 4; j++) {
                ss0 += c[i][j][0]*c[i][j][0] + c[i][j][1]*c[i][j][1];
                ss1 += c[i][j][2]*c[i][j][2] + c[i][j][3]*c[i][j][3];
            }
            int r0 = wm*64 + i*16 + gid;
            rs[r0*17 + wn*4 + tig]     = ss0;
            rs[(r0+8)*17 + wn*4 + tig] = ss1;
        }
        __syncthreads();
        if (tid < 128) {
            float ss = 0.f;
            #pragma unroll
            for (int x = 0; x < 16; x++) ss += rs[tid*17 + x];
            float inv = 1.f / fmaxf(sqrtf(ss), 1e-12f);
            if (mode == 1) inv *= 10.f;
            rinv[tid] = inv;
        }
        __syncthreads();
        #pragma unroll
        for (int i = 0; i < 4; i++) {
            int rr = wm*64 + i*16 + gid;
            float sc0 = rinv[rr], sc1 = rinv[rr+8];
            int r0 = m0 + rr;
            #pragma unroll
            for (int j = 0; j < 4; j++) {
                int colb = n0 + wn*32 + j*8 + tig*2;
                *(float2*)(Cz + (long)r0*N + colb) =
                    make_float2(c[i][j][0]*sc0, c[i][j][1]*sc0);
                *(float2*)(Cz + (long)(r0+8)*N + colb) =
                    make_float2(c[i][j][2]*sc1, c[i][j][3]*sc1);
            }
        }
    }
}

// ---------------- logits via 3xTF32 mma + fused reductions ---------------
__global__ __launch_bounds__(256, 1) void logits_mma()
{
    extern __shared__ uint32_t smu[];
    float* redL = (float*)(smu + 2*LOG_BUF);
    float* redM = redL + 256;
    float* redP = redM + 256;
    float* wred = redP + 256;

    int tile = blockIdx.x, b = blockIdx.y, kk = blockIdx.z;
    int t0 = tile * 64;
    int tid = threadIdx.x;
    int wid = tid >> 5, lane = tid & 31;
    int wm = wid >> 2, wn = wid & 3;
    int gid = lane >> 2, tig = lane & 3;

    const float* Ug = g_U + ((long)kk*32768 + (long)b*256 + t0) * 128;
    const float* Zg = g_z + (long)b * 32768;

    float c[2][8][4];
    #pragma unroll
    for (int i = 0; i < 2; i++)
        #pragma unroll
        for (int j = 0; j < 8; j++)
            #pragma unroll
            for (int q = 0; q < 4; q++) c[i][j][q] = 0.f;

    float4 rz[8], ru[2];
    #pragma unroll
    for (int l = 0; l < 8; l++) {
        int u = tid + l*256, r = u >> 3, c4 = u & 7;
        rz[l] = *(const float4*)(Zg + (long)r*128 + c4*4);
    }
    #pragma unroll
    for (int l = 0; l < 2; l++) {
        int u = tid + l*256, r = u >> 3, c4 = u & 7;
        ru[l] = *(const float4*)(Ug + (long)r*128 + c4*4);
    }
    #pragma unroll
    for (int l = 0; l < 8; l++) {
        int u = tid + l*256, r = u >> 3, c4 = u & 7;
        uint4 h, lo; cvt_hl(rz[l], h, lo);
        *(uint4*)(smu + 4608  + r*36 + c4*4) = h;
        *(uint4*)(smu + 13824 + r*36 + c4*4) = lo;
    }
    #pragma unroll
    for (int l = 0; l < 2; l++) {
        int u = tid + l*256, r = u >> 3, c4 = u & 7;
        uint4 h, lo; cvt_hl(ru[l], h, lo);
        *(uint4*)(smu + 0    + r*36 + c4*4) = h;
        *(uint4*)(smu + 2304 + r*36 + c4*4) = lo;
    }
    __syncthreads();

    #pragma unroll
    for (int kc = 0; kc < 4; kc++) {
        const uint32_t* base = smu + (kc & 1)*LOG_BUF;
        bool nxt = (kc < 3);
        if (nxt) {
            int k0 = (kc + 1) * 32;
            #pragma unroll
            for (int l = 0; l < 8; l++) {
                int u = tid + l*256, r = u >> 3, c4 = u & 7;
                rz[l] = *(const float4*)(Zg + (long)r*128 + k0 + c4*4);
            }
            #pragma unroll
            for (int l = 0; l < 2; l++) {
                int u = tid + l*256, r = u >> 3, c4 = u & 7;
                ru[l] = *(const float4*)(Ug + (long)r*128 + k0 + c4*4);
            }
        }
        #pragma unroll
        for (int ks = 0; ks < 4; ks++) {
            int k = ks * 8;
            uint32_t ah[2][4], al[2][4];
            #pragma unroll
            for (int i = 0; i < 2; i++) {
                int r0 = wm*32 + i*16 + gid;
                ah[i][0] = base[r0*36 + k + tig];
                ah[i][1] = base[(r0+8)*36 + k + tig];
                ah[i][2] = base[r0*36 + k + tig + 4];
                ah[i][3] = base[(r0+8)*36 + k + tig + 4];
                al[i][0] = base[2304 + r0*36 + k + tig];
                al[i][1] = base[2304 + (r0+8)*36 + k + tig];
                al[i][2] = base[2304 + r0*36 + k + tig + 4];
                al[i][3] = base[2304 + (r0+8)*36 + k + tig + 4];
            }
            #pragma unroll
            for (int j = 0; j < 8; j++) {
                int n = wn*64 + j*8 + gid;
                uint32_t bh[2], bl[2];
                bh[0] = base[4608 + n*36 + k + tig];
                bh[1] = base[4608 + n*36 + k + tig + 4];
                bl[0] = base[13824 + n*36 + k + tig];
                bl[1] = base[13824 + n*36 + k + tig + 4];
                #pragma unroll
                for (int i = 0; i < 2; i++) {
                    mma8(c[i][j], ah[i], bh);
                    mma8(c[i][j], ah[i], bl);
                    mma8(c[i][j], al[i], bh);
                }
            }
        }
        if (nxt) {
            uint32_t* nb = smu + ((kc + 1) & 1)*LOG_BUF;
            #pragma unroll
            for (int l = 0; l < 8; l++) {
                int u = tid + l*256, r = u >> 3, c4 = u & 7;
                uint4 h, lo; cvt_hl(rz[l], h, lo);
                *(uint4*)(nb + 4608  + r*36 + c4*4) = h;
                *(uint4*)(nb + 13824 + r*36 + c4*4) = lo;
            }
            #pragma unroll
            for (int l = 0; l < 2; l++) {
                int u = tid + l*256, r = u >> 3, c4 = u & 7;
                uint4 h, lo; cvt_hl(ru[l], h, lo);
                *(uint4*)(nb + 0    + r*36 + c4*4) = h;
                *(uint4*)(nb + 2304 + r*36 + c4*4) = lo;
            }
            __syncthreads();
        }
    }

    #pragma unroll
    for (int i = 0; i < 2; i++) {
        #pragma unroll
        for (int sub = 0; sub < 2; sub++) {
            int rrow = wm*32 + i*16 + sub*8 + gid;
            int spos = t0 + rrow + kk + 1;
            float lsum = 0.f, nmax = -3.0e38f, pos = -3.0e38f;
            #pragma unroll
            for (int j = 0; j < 8; j++) {
                #pragma unroll
                for (int p = 0; p < 2; p++) {
                    int col = wn*64 + j*8 + tig*2 + p;
                    float l = c[i][j][sub*2 + p];
                    lsum += __expf(l);
                    if (col == spos) pos = l;
                    else             nmax = fmaxf(nmax, l);
                }
            }
            #pragma unroll
            for (int o = 1; o <= 2; o <<= 1) {
                lsum += __shfl_xor_sync(0xffffffffu, lsum, o);
                nmax = fmaxf(nmax, __shfl_xor_sync(0xffffffffu, nmax, o));
                pos  = fmaxf(pos,  __shfl_xor_sync(0xffffffffu, pos,  o));
            }
            if (tig == 0) {
                redL[wn*64 + rrow] = lsum;
                redM[wn*64 + rrow] = nmax;
                redP[wn*64 + rrow] = pos;
            }
        }
    }
    __syncthreads();

    float loss_tot = 0.f, acc_tot = 0.f;
    if (tid < 64) {
        float ls = redL[tid] + redL[64+tid] + redL[128+tid] + redL[192+tid];
        float nm = fmaxf(fmaxf(redM[tid], redM[64+tid]), fmaxf(redM[128+tid], redM[192+tid]));
        float ps = fmaxf(fmaxf(redP[tid], redP[64+tid]), fmaxf(redP[128+tid], redP[192+tid]));
        int t = t0 + tid;
        if (t < TP) {
            loss_tot = logf(ls) - ps;
            acc_tot  = (ps >= nm) ? 1.f : 0.f;
        }
    }
    if (wid < 2) {
        #pragma unroll
        for (int o = 16; o; o >>= 1) {
            loss_tot += __shfl_xor_sync(0xffffffffu, loss_tot, o);
            acc_tot  += __shfl_xor_sync(0xffffffffu, acc_tot,  o);
        }
        if (lane == 0) { wred[wid*2] = loss_tot; wred[wid*2+1] = acc_tot; }
    }
    __syncthreads();
    if (tid == 0) {
        long bid = ((long)kk*128 + b)*4 + tile;
        g_part[bid*2]   = wred[0] + wred[2];
        g_part[bid*2+1] = wred[1] + wred[3];
    }
}

// ---------------- GRU v3: register-stationary W, k-split threads ---------
// 16 clusters x 8 CTAs. CTA rank owns channels [32r,32r+32). Thread
// (c = tid>>3, ks = tid&7) holds W_hh[{c,256+c,512+c}+co][ks*32..+32) in
// registers and computes 3x8 partial dots over its k-slice; butterfly over
// the 8 ks lanes; lane b==ks applies gates and pushes h via DSMEM.
__global__ __launch_bounds__(256, 1) __cluster_dims__(8, 1, 1)
void gru3(const float* __restrict__ Whh, const float* __restrict__ bhh)
{
    extern __shared__ float s[];
    float* hb = s;                         // [2][8][264]

    int tid  = threadIdx.x;
    int rank = blockIdx.x & 7;
    int cl   = blockIdx.x >> 3;
    int co   = rank * 32;
    int b0   = cl * 8;
    int c    = tid >> 3, ks = tid & 7;

    // W registers: 3 gates x 16 f32x2 pairs over k in [ks*32, ks*32+32)
    unsigned long long w0r[16], w1r[16], w2r[16];
    {
        const float* p0 = Whh + ((long)(0*256 + co + c))*256 + ks*32;
        const float* p1 = Whh + ((long)(1*256 + co + c))*256 + ks*32;
        const float* p2 = Whh + ((long)(2*256 + co + c))*256 + ks*32;
        #pragma unroll
        for (int i = 0; i < 16; i++) {
            w0r[i] = *(const unsigned long long*)(p0 + i*2);
            w1r[i] = *(const unsigned long long*)(p1 + i*2);
            w2r[i] = *(const unsigned long long*)(p2 + i*2);
        }
    }
    float bhr0 = bhh[co + c], bhr1 = bhh[256 + co + c], bhr2 = bhh[512 + co + c];

    for (int i = tid; i < 2*8*264; i += 256) hb[i] = 0.f;

    const float* gxp = g_gx + ((long)(b0 + ks) * 256) * 768 + co + c;
    float*       cp  = g_c  + ((long)(b0 + ks) * 256) * 256 + co + c;
    uint32_t ladr = s2u(hb) + (uint32_t)((ks*264 + co + c) * 4);
    uint32_t radr[8];
    #pragma unroll
    for (int r = 0; r < 8; r++) radr[r] = mapa_u32(ladr, r);

    float h_old = 0.f;
    __syncthreads();
    asm volatile("barrier.cluster.arrive.aligned;" ::: "memory");
    asm volatile("barrier.cluster.wait.aligned;"   ::: "memory");

    for (int t = 0; t < 256; t++) {
        int p = t & 1, pn = p ^ 1;
        float xr = gxp[(long)t*768];
        float xz = gxp[(long)t*768 + 256];
        float xn = gxp[(long)t*768 + 512];

        const float* hp = hb + p*2112 + ks*32;
        float sg0[8], sg1[8], sg2[8];
        #pragma unroll
        for (int b = 0; b < 8; b++) {
            const float* hq = hp + b*264;
            unsigned long long a0 = 0ULL, a1 = 0ULL, a2 = 0ULL;
            #pragma unroll
            for (int j4 = 0; j4 < 8; j4++) {
                int jr = (j4 + ks) & 7;
                ulonglong2 h4 = *(const ulonglong2*)(hq + jr*4);
                FMA2(a0, w0r[jr*2], h4.x); FMA2(a0, w0r[jr*2+1], h4.y);
                FMA2(a1, w1r[jr*2], h4.x); FMA2(a1, w1r[jr*2+1], h4.y);
                FMA2(a2, w2r[jr*2], h4.x); FMA2(a2, w2r[jr*2+1], h4.y);
            }
            sg0[b] = pairsum(a0); sg1[b] = pairsum(a1); sg2[b] = pairsum(a2);
        }
        // butterfly over the 8 ks lanes (low 3 lane bits)
        #pragma unroll
        for (int o = 1; o <= 4; o <<= 1) {
            #pragma unroll
            for (int b = 0; b < 8; b++) {
                sg0[b] += __shfl_xor_sync(0xffffffffu, sg0[b], o);
                sg1[b] += __shfl_xor_sync(0xffffffffu, sg1[b], o);
                sg2[b] += __shfl_xor_sync(0xffffffffu, sg2[b], o);
            }
        }
        // select b == ks
        float hr = 0.f, hz = 0.f, hn = 0.f;
        #pragma unroll
        for (int b = 0; b < 8; b++) {
            if (b == ks) { hr = sg0[b]; hz = sg1[b]; hn = sg2[b]; }
        }
        hr += bhr0; hz += bhr1; hn += bhr2;

        float rg = fsig(xr + hr);
        float zg = fsig(xz + hz);
        float ng = ftanh(xn + rg*hn);
        float hnew = (1.f - zg)*ng + zg*h_old;
        h_old = hnew;

        uint32_t off = (uint32_t)(pn * 8448);       // 2112 floats
        #pragma unroll
        for (int r = 0; r < 8; r++) st_cluster_f32(radr[r] + off, hnew);
        cp[(long)t*256] = hnew;

        asm volatile("barrier.cluster.arrive.aligned;" ::: "memory");
        asm volatile("barrier.cluster.wait.aligned;"   ::: "memory");
    }
}

// ---------------- final reduction ---------------------------------------
__global__ void final_kernel(float* __restrict__ out)
{
    __shared__ float sl[256], sa[256];
    int tid = threadIdx.x;
    float L = 0.f, A = 0.f;
    for (int i = tid; i < 6144; i += 256) { L += g_part[i*2]; A += g_part[i*2+1]; }
    sl[tid] = L; sa[tid] = A;
    __syncthreads();
    for (int o = 128; o; o >>= 1) {
        if (tid < o) { sl[tid] += sl[tid+o]; sa[tid] += sa[tid+o]; }
        __syncthreads();
    }
    if (tid == 0) {
        out[0] = sl[0] / (float)NROWS_L;
        out[1] = sa[0] / (float)NROWS_L * 100.f;
    }
}

// ---------------- copy z and c into d_out (8B-aligned dst) ---------------
__global__ void copyout_kernel(float* __restrict__ out)
{
    long i = (long)blockIdx.x * 256 + threadIdx.x;
    float2* dst = (float2*)(out + 2);
    const long NZ2 = 2097152;
    const long NC2 = 4194304;
    if (i < NZ2) {
        dst[i] = ((const float2*)g_z)[i];
    } else if (i < NZ2 + NC2) {
        dst[i] = ((const float2*)g_c)[i - NZ2];
    }
}

// ---------------- host launcher ------------------------------------------
extern "C" void kernel_launch(void* const* d_in, const int* in_sizes, int n_in,
                              void* d_out, int out_size)
{
    const float* rr  = (const float*)d_in[0];
    const float* w1  = (const float*)d_in[1];
    const float* b1  = (const float*)d_in[2];
    const float* w2  = (const float*)d_in[3];
    const float* b2  = (const float*)d_in[4];
    const float* Wih = (const float*)d_in[5];
    const float* Whh = (const float*)d_in[6];
    const float* bih = (const float*)d_in[7];
    const float* bhh = (const float*)d_in[8];
    const float* Wkw = (const float*)d_in[9];
    const float* Wkb = (const float*)d_in[10];

    float* out = (float*)d_out;

    float *pz, *pc, *ph1, *pgx, *pU, *pw1T, *pw2T, *pWkT;
    cudaGetSymbolAddress((void**)&pz,   g_z);
    cudaGetSymbolAddress((void**)&pc,   g_c);
    cudaGetSymbolAddress((void**)&ph1,  g_h1);
    cudaGetSymbolAddress((void**)&pgx,  g_gx);
    cudaGetSymbolAddress((void**)&pU,   g_U);
    cudaGetSymbolAddress((void**)&pw1T, g_w1T);
    cudaGetSymbolAddress((void**)&pw2T, g_w2T);
    cudaGetSymbolAddress((void**)&pWkT, g_WkT);

    cudaFuncSetAttribute(logits_mma, cudaFuncAttributeMaxDynamicSharedMemorySize, LOG_SMEM);
    cudaFuncSetAttribute(gru3,       cudaFuncAttributeMaxDynamicSharedMemorySize, GRU3_SMEM);
    cudaFuncSetAttribute(mma_gemm,   cudaFuncAttributeMaxDynamicSharedMemorySize, GEMM_SMEM);

    // 0. weight transposes
    prep_transpose<<<1536, 256>>>(w1, w2, Wkw);
    // 1. encoder layer 1 (relu)
    mma_gemm<<<dim3(2, 256, 1), 256, GEMM_SMEM>>>(
        rr, pw1T, b1, ph1, N_BT, 256, 256, 1, 0, 0, 0, 0);
    // 2. encoder layer 2 -> normalized z (mode 2)
    mma_gemm<<<dim3(1, 256, 1), 256, GEMM_SMEM>>>(
        ph1, pw2T, b2, pz, N_BT, 128, 256, 0, 2, 0, 0, 0);
    // 3. gx = z @ W_ih^T + b_ih
    mma_gemm<<<dim3(6, 256, 1), 256, GEMM_SMEM>>>(
        pz, Wih, bih, pgx, N_BT, 768, 128, 0, 0, 0, 0, 0);
    // 4. GRU v3 (register-stationary W)
    gru3<<<128, 256, GRU3_SMEM>>>(Whh, bhh);
    // 5. U[k] = rowscale10(c @ Wk_w[k] + Wk_b[k])  (mode 1)
    mma_gemm<<<dim3(1, 256, 12), 256, GEMM_SMEM>>>(
        pc, pWkT, Wkb, pU, N_BT, 128, 256, 0, 1,
        32768L, 128L, (long)N_BT * 128);
    // 6. fused logits + reductions (tensor-core)
    logits_mma<<<dim3(4, 128, 12), 256, LOG_SMEM>>>();
    // 7. final loss/accuracy
    final_kernel<<<1, 256>>>(out);
    // 8. copy z_seq and c_seq into d_out
    copyout_kernel<<<24576, 256>>>(out);
}

// round 10
// speedup vs baseline: 1.8336x; 1.0056x over previous
#include <cuda_runtime.h>
#include <math.h>
#include <stdint.h>

// B=128, T=256, W=256, D=128, C=256, K=12, Tp=244, TEMP=0.1
#define N_BT     32768
#define TP       244
#define NROWS_L  374784
// gemm smem: 2 buf x 4 arrays x 128x36 words + 128 bias
#define GEMM_SMEM ((2*4*4608 + 128)*4)
// logits smem
#define LOG_BUF   (2*2304 + 2*9216)
#define LOG_SMEM  ((2*LOG_BUF + 3*256 + 64)*4)
// GRU4 smem: hb [2][2048] words (h permuted layout [b][j4][ks][4])
#define GRU4_SMEM (2*2048*4)

// ---------------- packed f32x2 helpers -----------------------------------
#define FMA2(d,a,b) asm("fma.rn.f32x2 %0, %1, %2, %0;" : "+l"(d) : "l"(a), "l"(b))
__device__ __forceinline__ void unpack2(unsigned long long v, float& lo, float& hi) {
    asm("mov.b64 {%0, %1}, %2;" : "=f"(lo), "=f"(hi) : "l"(v));
}
__device__ __forceinline__ float pairsum(unsigned long long v) {
    float a, b; unpack2(v, a, b); return a + b;
}
__device__ __forceinline__ uint32_t s2u(const void* p) {
    uint32_t a; asm("{ .reg .u64 t; cvta.to.shared.u64 t, %1; cvt.u32.u64 %0, t; }" : "=r"(a) : "l"(p));
    return a;
}
__device__ __forceinline__ uint32_t mapa_u32(uint32_t addr, uint32_t rank) {
    uint32_t r; asm("mapa.shared::cluster.u32 %0, %1, %2;" : "=r"(r) : "r"(addr), "r"(rank));
    return r;
}
__device__ __forceinline__ void st_cluster_f32(uint32_t addr, float v) {
    asm volatile("st.shared::cluster.f32 [%0], %1;" :: "r"(addr), "f"(v) : "memory");
}
__device__ __forceinline__ float fsig(float x)  { return 1.f / (1.f + __expf(-x)); }
__device__ __forceinline__ float ftanh(float x) { return 1.f - 2.f / (1.f + __expf(2.f*x)); }

// ---------------- tf32 mma helpers ---------------------------------------
__device__ __forceinline__ uint32_t f2tf(float x) {
    uint32_t r; asm("cvt.rna.tf32.f32 %0, %1;" : "=r"(r) : "f"(x)); return r;
}
__device__ __forceinline__ void cvt_hl(float4 x, uint4& h, uint4& l) {
    h.x = f2tf(x.x); l.x = f2tf(x.x - __uint_as_float(h.x));
    h.y = f2tf(x.y); l.y = f2tf(x.y - __uint_as_float(h.y));
    h.z = f2tf(x.z); l.z = f2tf(x.z - __uint_as_float(h.z));
    h.w = f2tf(x.w); l.w = f2tf(x.w - __uint_as_float(h.w));
}
__device__ __forceinline__ void mma8(float* c, const uint32_t* a, const uint32_t* b) {
    asm volatile("mma.sync.aligned.m16n8k8.row.col.f32.tf32.tf32.f32 "
        "{%0,%1,%2,%3}, {%4,%5,%6,%7}, {%8,%9}, {%0,%1,%2,%3};"
        : "+f"(c[0]), "+f"(c[1]), "+f"(c[2]), "+f"(c[3])
        : "r"(a[0]), "r"(a[1]), "r"(a[2]), "r"(a[3]), "r"(b[0]), "r"(b[1]));
}

// ---------------- scratch ------------------------------------------------
__device__ __align__(16) float g_z   [4194304];   // [32768,128] normalized z
__device__ __align__(16) float g_c   [8388608];   // [32768,256] c_seq
__device__ __align__(16) float g_h1  [8388608];   // [32768,256]
__device__ __align__(16) float g_gx  [25165824];  // [32768,768]
__device__ __align__(16) float g_U   [50331648];  // [12,32768,128] rows scaled by 10/||.||
__device__ __align__(16) float g_w1T [65536];
__device__ __align__(16) float g_w2T [32768];
__device__ __align__(16) float g_WkT [393216];
__device__ __align__(16) float g_part[12288];

// ---------------- prep: transposes --------------------------------------
__global__ void prep_transpose(const float* __restrict__ w1, const float* __restrict__ w2,
                               const float* __restrict__ wk)
{
    long i = (long)blockIdx.x * 256 + threadIdx.x;
    if (i < 65536) {
        int n = (int)(i >> 8), k = (int)(i & 255);
        g_w1T[n*256 + k] = w1[k*256 + n];
    }
    if (i < 32768) {
        int n = (int)(i >> 8), k = (int)(i & 255);
        g_w2T[n*256 + k] = w2[k*128 + n];
    }
    if (i < 393216) {
        long kk = i / 32768; long r = i % 32768;
        int d = (int)(r >> 8), c = (int)(r & 255);
        g_WkT[kk*32768 + d*256 + c] = wk[kk*32768 + c*128 + d];
    }
}

// ---------------- 3xTF32 mma.sync NT-GEMM (hi/lo staged in smem) ---------
__global__ __launch_bounds__(256, 1) void mma_gemm(
    const float* __restrict__ A, const float* __restrict__ Bm,
    const float* __restrict__ bias, float* __restrict__ Cm,
    int M, int N, int K, int relu, int mode,
    long sB, long sBias, long sC)
{
    extern __shared__ uint32_t smu[];
    float* sbias = (float*)(smu + 36864);
    float* rs    = (float*)smu;          // overlay [128][17]
    float* rinv  = (float*)(smu + 2176);

    const float* Bz = Bm  + (long)blockIdx.z * sB;
    const float* bz = bias + (long)blockIdx.z * sBias;
    float*       Cz = Cm  + (long)blockIdx.z * sC;
    int m0 = blockIdx.y * 128, n0 = blockIdx.x * 128;

    int tid = threadIdx.x;
    int wid = tid >> 5, lane = tid & 31;
    int wm = wid >> 2, wn = wid & 3;
    int gid = lane >> 2, tig = lane & 3;

    if (tid < 128) sbias[tid] = bz[n0 + tid];

    const float* Ag = A  + (long)m0 * K;
    const float* Bg = Bz + (long)n0 * K;

    float c[4][4][4];
    #pragma unroll
    for (int i = 0; i < 4; i++)
        #pragma unroll
        for (int j = 0; j < 4; j++)
            #pragma unroll
            for (int q = 0; q < 4; q++) c[i][j][q] = 0.f;

    float4 ra[4], rb[4];
    #pragma unroll
    for (int l = 0; l < 4; l++) {
        int u = tid + l*256, r = u >> 3, c4 = u & 7;
        ra[l] = *(const float4*)(Ag + (long)r*K + c4*4);
        rb[l] = *(const float4*)(Bg + (long)r*K + c4*4);
    }
    #pragma unroll
    for (int l = 0; l < 4; l++) {
        int u = tid + l*256, r = u >> 3, c4 = u & 7;
        uint4 h, lo;
        cvt_hl(ra[l], h, lo);
        *(uint4*)(smu + 0    + r*36 + c4*4) = h;
        *(uint4*)(smu + 4608 + r*36 + c4*4) = lo;
        cvt_hl(rb[l], h, lo);
        *(uint4*)(smu + 9216  + r*36 + c4*4) = h;
        *(uint4*)(smu + 13824 + r*36 + c4*4) = lo;
    }
    __syncthreads();

    int NC = K >> 5;
    for (int kc = 0; kc < NC; kc++) {
        const uint32_t* base = smu + (kc & 1)*18432;
        bool nxt = (kc + 1 < NC);
        if (nxt) {
            int k0 = (kc + 1) * 32;
            #pragma unroll
            for (int l = 0; l < 4; l++) {
                int u = tid + l*256, r = u >> 3, c4 = u & 7;
                ra[l] = *(const float4*)(Ag + (long)r*K + k0 + c4*4);
                rb[l] = *(const float4*)(Bg + (long)r*K + k0 + c4*4);
            }
        }
        #pragma unroll
        for (int ks = 0; ks < 4; ks++) {
            int k = ks * 8;
            uint32_t ah[4][4], al[4][4];
            #pragma unroll
            for (int i = 0; i < 4; i++) {
                int r0 = wm*64 + i*16 + gid;
                ah[i][0] = base[r0*36 + k + tig];
                ah[i][1] = base[(r0+8)*36 + k + tig];
                ah[i][2] = base[r0*36 + k + tig + 4];
                ah[i][3] = base[(r0+8)*36 + k + tig + 4];
                al[i][0] = base[4608 + r0*36 + k + tig];
                al[i][1] = base[4608 + (r0+8)*36 + k + tig];
                al[i][2] = base[4608 + r0*36 + k + tig + 4];
                al[i][3] = base[4608 + (r0+8)*36 + k + tig + 4];
            }
            #pragma unroll
            for (int j = 0; j < 4; j++) {
                int n = wn*32 + j*8 + gid;
                uint32_t bh[2], bl[2];
                bh[0] = base[9216 + n*36 + k + tig];
                bh[1] = base[9216 + n*36 + k + tig + 4];
                bl[0] = base[13824 + n*36 + k + tig];
                bl[1] = base[13824 + n*36 + k + tig + 4];
                #pragma unroll
                for (int i = 0; i < 4; i++) {
                    mma8(c[i][j], ah[i], bh);
                    mma8(c[i][j], ah[i], bl);
                    mma8(c[i][j], al[i], bh);
                }
            }
        }
        if (nxt) {
            uint32_t* nb = smu + ((kc + 1) & 1)*18432;
            #pragma unroll
            for (int l = 0; l < 4; l++) {
                int u = tid + l*256, r = u >> 3, c4 = u & 7;
                uint4 h, lo;
                cvt_hl(ra[l], h, lo);
                *(uint4*)(nb + 0    + r*36 + c4*4) = h;
                *(uint4*)(nb + 4608 + r*36 + c4*4) = lo;
                cvt_hl(rb[l], h, lo);
                *(uint4*)(nb + 9216  + r*36 + c4*4) = h;
                *(uint4*)(nb + 13824 + r*36 + c4*4) = lo;
            }
            __syncthreads();
        }
    }

    #pragma unroll
    for (int i = 0; i < 4; i++)
        #pragma unroll
        for (int j = 0; j < 4; j++) {
            int colb = wn*32 + j*8 + tig*2;
            c[i][j][0] += sbias[colb]; c[i][j][1] += sbias[colb+1];
            c[i][j][2] += sbias[colb]; c[i][j][3] += sbias[colb+1];
        }

    if (mode == 0) {
        #pragma unroll
        for (int i = 0; i < 4; i++) {
            int r0 = m0 + wm*64 + i*16 + gid;
            #pragma unroll
            for (int j = 0; j < 4; j++) {
                int colb = n0 + wn*32 + j*8 + tig*2;
                float2 v0 = make_float2(c[i][j][0], c[i][j][1]);
                float2 v1 = make_float2(c[i][j][2], c[i][j][3]);
                if (relu) {
                    v0.x = fmaxf(v0.x, 0.f); v0.y = fmaxf(v0.y, 0.f);
                    v1.x = fmaxf(v1.x, 0.f); v1.y = fmaxf(v1.y, 0.f);
                }
                *(float2*)(Cz + (long)r0*N + colb)     = v0;
                *(float2*)(Cz + (long)(r0+8)*N + colb) = v1;
            }
        }
    } else {
        __syncthreads();
        #pragma unroll
        for (int i = 0; i < 4; i++) {
            float ss0 = 0.f, ss1 = 0.f;
            #pragma unroll
            for (int j = 0; j < 4; j++) {
                ss0 += c[i][j][0]*c[i][j][0] + c[i][j][1]*c[i][j][1];
                ss1 += c[i][j][2]*c[i][j][2] + c[i][j][3]*c[i][j][3];
            }
            int r0 = wm*64 + i*16 + gid;
            rs[r0*17 + wn*4 + tig]     = ss0;
            rs[(r0+8)*17 + wn*4 + tig] = ss1;
        }
        __syncthreads();
        if (tid < 128) {
            float ss = 0.f;
            #pragma unroll
            for (int x = 0; x < 16; x++) ss += rs[tid*17 + x];
            float inv = 1.f / fmaxf(sqrtf(ss), 1e-12f);
            if (mode == 1) inv *= 10.f;
            rinv[tid] = inv;
        }
        __syncthreads();
        #pragma unroll
        for (int i = 0; i < 4; i++) {
            int rr = wm*64 + i*16 + gid;
            float sc0 = rinv[rr], sc1 = rinv[rr+8];
            int r0 = m0 + rr;
            #pragma unroll
            for (int j = 0; j < 4; j++) {
                int colb = n0 + wn*32 + j*8 + tig*2;
                *(float2*)(Cz + (long)r0*N + colb) =
                    make_float2(c[i][j][0]*sc0, c[i][j][1]*sc0);
                *(float2*)(Cz + (long)(r0+8)*N + colb) =
                    make_float2(c[i][j][2]*sc1, c[i][j][3]*sc1);
            }
        }
    }
}

// ---------------- logits via 3xTF32 mma + fused reductions ---------------
__global__ __launch_bounds__(256, 1) void logits_mma()
{
    extern __shared__ uint32_t smu[];
    float* redL = (float*)(smu + 2*LOG_BUF);
    float* redM = redL + 256;
    float* redP = redM + 256;
    float* wred = redP + 256;

    int tile = blockIdx.x, b = blockIdx.y, kk = blockIdx.z;
    int t0 = tile * 64;
    int tid = threadIdx.x;
    int wid = tid >> 5, lane = tid & 31;
    int wm = wid >> 2, wn = wid & 3;
    int gid = lane >> 2, tig = lane & 3;

    const float* Ug = g_U + ((long)kk*32768 + (long)b*256 + t0) * 128;
    const float* Zg = g_z + (long)b * 32768;

    float c[2][8][4];
    #pragma unroll
    for (int i = 0; i < 2; i++)
        #pragma unroll
        for (int j = 0; j < 8; j++)
            #pragma unroll
            for (int q = 0; q < 4; q++) c[i][j][q] = 0.f;

    float4 rz[8], ru[2];
    #pragma unroll
    for (int l = 0; l < 8; l++) {
        int u = tid + l*256, r = u >> 3, c4 = u & 7;
        rz[l] = *(const float4*)(Zg + (long)r*128 + c4*4);
    }
    #pragma unroll
    for (int l = 0; l < 2; l++) {
        int u = tid + l*256, r = u >> 3, c4 = u & 7;
        ru[l] = *(const float4*)(Ug + (long)r*128 + c4*4);
    }
    #pragma unroll
    for (int l = 0; l < 8; l++) {
        int u = tid + l*256, r = u >> 3, c4 = u & 7;
        uint4 h, lo; cvt_hl(rz[l], h, lo);
        *(uint4*)(smu + 4608  + r*36 + c4*4) = h;
        *(uint4*)(smu + 13824 + r*36 + c4*4) = lo;
    }
    #pragma unroll
    for (int l = 0; l < 2; l++) {
        int u = tid + l*256, r = u >> 3, c4 = u & 7;
        uint4 h, lo; cvt_hl(ru[l], h, lo);
        *(uint4*)(smu + 0    + r*36 + c4*4) = h;
        *(uint4*)(smu + 2304 + r*36 + c4*4) = lo;
    }
    __syncthreads();

    #pragma unroll
    for (int kc = 0; kc < 4; kc++) {
        const uint32_t* base = smu + (kc & 1)*LOG_BUF;
        bool nxt = (kc < 3);
        if (nxt) {
            int k0 = (kc + 1) * 32;
            #pragma unroll
            for (int l = 0; l < 8; l++) {
                int u = tid + l*256, r = u >> 3, c4 = u & 7;
                rz[l] = *(const float4*)(Zg + (long)r*128 + k0 + c4*4);
            }
            #pragma unroll
            for (int l = 0; l < 2; l++) {
                int u = tid + l*256, r = u >> 3, c4 = u & 7;
                ru[l] = *(const float4*)(Ug + (long)r*128 + k0 + c4*4);
            }
        }
        #pragma unroll
        for (int ks = 0; ks < 4; ks++) {
            int k = ks * 8;
            uint32_t ah[2][4], al[2][4];
            #pragma unroll
            for (int i = 0; i < 2; i++) {
                int r0 = wm*32 + i*16 + gid;
                ah[i][0] = base[r0*36 + k + tig];
                ah[i][1] = base[(r0+8)*36 + k + tig];
                ah[i][2] = base[r0*36 + k + tig + 4];
                ah[i][3] = base[(r0+8)*36 + k + tig + 4];
                al[i][0] = base[2304 + r0*36 + k + tig];
                al[i][1] = base[2304 + (r0+8)*36 + k + tig];
                al[i][2] = base[2304 + r0*36 + k + tig + 4];
                al[i][3] = base[2304 + (r0+8)*36 + k + tig + 4];
            }
            #pragma unroll
            for (int j = 0; j < 8; j++) {
                int n = wn*64 + j*8 + gid;
                uint32_t bh[2], bl[2];
                bh[0] = base[4608 + n*36 + k + tig];
                bh[1] = base[4608 + n*36 + k + tig + 4];
                bl[0] = base[13824 + n*36 + k + tig];
                bl[1] = base[13824 + n*36 + k + tig + 4];
                #pragma unroll
                for (int i = 0; i < 2; i++) {
                    mma8(c[i][j], ah[i], bh);
                    mma8(c[i][j], ah[i], bl);
                    mma8(c[i][j], al[i], bh);
                }
            }
        }
        if (nxt) {
            uint32_t* nb = smu + ((kc + 1) & 1)*LOG_BUF;
            #pragma unroll
            for (int l = 0; l < 8; l++) {
                int u = tid + l*256, r = u >> 3, c4 = u & 7;
                uint4 h, lo; cvt_hl(rz[l], h, lo);
                *(uint4*)(nb + 4608  + r*36 + c4*4) = h;
                *(uint4*)(nb + 13824 + r*36 + c4*4) = lo;
            }
            #pragma unroll
            for (int l = 0; l < 2; l++) {
                int u = tid + l*256, r = u >> 3, c4 = u & 7;
                uint4 h, lo; cvt_hl(ru[l], h, lo);
                *(uint4*)(nb + 0    + r*36 + c4*4) = h;
                *(uint4*)(nb + 2304 + r*36 + c4*4) = lo;
            }
            __syncthreads();
        }
    }

    #pragma unroll
    for (int i = 0; i < 2; i++) {
        #pragma unroll
        for (int sub = 0; sub < 2; sub++) {
            int rrow = wm*32 + i*16 + sub*8 + gid;
            int spos = t0 + rrow + kk + 1;
            float lsum = 0.f, nmax = -3.0e38f, pos = -3.0e38f;
            #pragma unroll
            for (int j = 0; j < 8; j++) {
                #pragma unroll
                for (int p = 0; p < 2; p++) {
                    int col = wn*64 + j*8 + tig*2 + p;
                    float l = c[i][j][sub*2 + p];
                    lsum += __expf(l);
                    if (col == spos) pos = l;
                    else             nmax = fmaxf(nmax, l);
                }
            }
            #pragma unroll
            for (int o = 1; o <= 2; o <<= 1) {
                lsum += __shfl_xor_sync(0xffffffffu, lsum, o);
                nmax = fmaxf(nmax, __shfl_xor_sync(0xffffffffu, nmax, o));
                pos  = fmaxf(pos,  __shfl_xor_sync(0xffffffffu, pos,  o));
            }
            if (tig == 0) {
                redL[wn*64 + rrow] = lsum;
                redM[wn*64 + rrow] = nmax;
                redP[wn*64 + rrow] = pos;
            }
        }
    }
    __syncthreads();

    float loss_tot = 0.f, acc_tot = 0.f;
    if (tid < 64) {
        float ls = redL[tid] + redL[64+tid] + redL[128+tid] + redL[192+tid];
        float nm = fmaxf(fmaxf(redM[tid], redM[64+tid]), fmaxf(redM[128+tid], redM[192+tid]));
        float ps = fmaxf(fmaxf(redP[tid], redP[64+tid]), fmaxf(redP[128+tid], redP[192+tid]));
        int t = t0 + tid;
        if (t < TP) {
            loss_tot = logf(ls) - ps;
            acc_tot  = (ps >= nm) ? 1.f : 0.f;
        }
    }
    if (wid < 2) {
        #pragma unroll
        for (int o = 16; o; o >>= 1) {
            loss_tot += __shfl_xor_sync(0xffffffffu, loss_tot, o);
            acc_tot  += __shfl_xor_sync(0xffffffffu, acc_tot,  o);
        }
        if (lane == 0) { wred[wid*2] = loss_tot; wred[wid*2+1] = acc_tot; }
    }
    __syncthreads();
    if (tid == 0) {
        long bid = ((long)kk*128 + b)*4 + tile;
        g_part[bid*2]   = wred[0] + wred[2];
        g_part[bid*2+1] = wred[1] + wred[3];
    }
}

// ---------------- GRU v4: register W + permuted h layout -----------------
// Like gru3, but h stored as hs[b][j4][ks][4] so each LDS.128 of h is one
// 128B row (1 wavefront): lanes = 8 ks slices x 16B consecutive, 4 c-lanes
// broadcast. Writers compute their permuted slot once.
__global__ __launch_bounds__(256, 1) __cluster_dims__(8, 1, 1)
void gru4(const float* __restrict__ Whh, const float* __restrict__ bhh)
{
    extern __shared__ float s[];
    float* hb = s;                         // [2][2048], layout [b][j4][ks][4]

    int tid  = threadIdx.x;
    int rank = blockIdx.x & 7;
    int cl   = blockIdx.x >> 3;
    int co   = rank * 32;
    int b0   = cl * 8;
    int c    = tid >> 3, ks = tid & 7;

    // W registers: 3 gates x 16 f32x2 pairs over k in [ks*32, ks*32+32)
    unsigned long long w0r[16], w1r[16], w2r[16];
    {
        const float* p0 = Whh + ((long)(0*256 + co + c))*256 + ks*32;
        const float* p1 = Whh + ((long)(1*256 + co + c))*256 + ks*32;
        const float* p2 = Whh + ((long)(2*256 + co + c))*256 + ks*32;
        #pragma unroll
        for (int i = 0; i < 16; i++) {
            w0r[i] = *(const unsigned long long*)(p0 + i*2);
            w1r[i] = *(const unsigned long long*)(p1 + i*2);
            w2r[i] = *(const unsigned long long*)(p2 + i*2);
        }
    }
    float bhr0 = bhh[co + c], bhr1 = bhh[256 + co + c], bhr2 = bhh[512 + co + c];

    for (int i = tid; i < 2*2048; i += 256) hb[i] = 0.f;

    // this thread's output: channel k_g = co + c, batch b = ks
    const float* gxp = g_gx + ((long)(b0 + ks) * 256) * 768 + co + c;
    float*       cp  = g_c  + ((long)(b0 + ks) * 256) * 256 + co + c;
    // permuted slot for channel k_g in batch ks: [b=ks][j4=(k>>2)&7][ks_w=k>>5][w4=k&3]
    int kg = co + c;
    int slot = ((ks*8 + ((kg >> 2) & 7))*8 + (kg >> 5))*4 + (kg & 3);
    uint32_t ladr = s2u(hb) + (uint32_t)(slot * 4);
    uint32_t radr[8];
    #pragma unroll
    for (int r = 0; r < 8; r++) radr[r] = mapa_u32(ladr, r);

    float h_old = 0.f;
    __syncthreads();
    asm volatile("barrier.cluster.arrive.aligned;" ::: "memory");
    asm volatile("barrier.cluster.wait.aligned;"   ::: "memory");

    for (int t = 0; t < 256; t++) {
        int p = t & 1, pn = p ^ 1;
        float xr = gxp[(long)t*768];
        float xz = gxp[(long)t*768 + 256];
        float xn = gxp[(long)t*768 + 512];

        // read h[b][ks*32 + j4*4 .. +4] at hs[b][j4][ks][0..3]
        const float* hp = hb + p*2048 + ks*4;
        float sg0[8], sg1[8], sg2[8];
        #pragma unroll
        for (int b = 0; b < 8; b++) {
            const float* hq = hp + b*256;
            unsigned long long a0 = 0ULL, a1 = 0ULL, a2 = 0ULL;
            #pragma unroll
            for (int j4 = 0; j4 < 8; j4++) {
                ulonglong2 h4 = *(const ulonglong2*)(hq + j4*32);
                FMA2(a0, w0r[j4*2], h4.x); FMA2(a0, w0r[j4*2+1], h4.y);
                FMA2(a1, w1r[j4*2], h4.x); FMA2(a1, w1r[j4*2+1], h4.y);
                FMA2(a2, w2r[j4*2], h4.x); FMA2(a2, w2r[j4*2+1], h4.y);
            }
            sg0[b] = pairsum(a0); sg1[b] = pairsum(a1); sg2[b] = pairsum(a2);
        }
        // butterfly over the 8 ks lanes (low 3 lane bits)
        #pragma unroll
        for (int o = 1; o <= 4; o <<= 1) {
            #pragma unroll
            for (int b = 0; b < 8; b++) {
                sg0[b] += __shfl_xor_sync(0xffffffffu, sg0[b], o);
                sg1[b] += __shfl_xor_sync(0xffffffffu, sg1[b], o);
                sg2[b] += __shfl_xor_sync(0xffffffffu, sg2[b], o);
            }
        }
        float hr = 0.f, hz = 0.f, hn = 0.f;
        #pragma unroll
        for (int b = 0; b < 8; b++) {
            if (b == ks) { hr = sg0[b]; hz = sg1[b]; hn = sg2[b]; }
        }
        hr += bhr0; hz += bhr1; hn += bhr2;

        float rg = fsig(xr + hr);
        float zg = fsig(xz + hz);
        float ng = ftanh(xn + rg*hn);
        float hnew = (1.f - zg)*ng + zg*h_old;
        h_old = hnew;

        uint32_t off = (uint32_t)(pn * 8192);       // 2048 floats
        #pragma unroll
        for (int r = 0; r < 8; r++) st_cluster_f32(radr[r] + off, hnew);
        cp[(long)t*256] = hnew;

        asm volatile("barrier.cluster.arrive.aligned;" ::: "memory");
        asm volatile("barrier.cluster.wait.aligned;"   ::: "memory");
    }
}

// ---------------- final reduction ---------------------------------------
__global__ void final_kernel(float* __restrict__ out)
{
    __shared__ float sl[256], sa[256];
    int tid = threadIdx.x;
    float L = 0.f, A = 0.f;
    for (int i = tid; i < 6144; i += 256) { L += g_part[i*2]; A += g_part[i*2+1]; }
    sl[tid] = L; sa[tid] = A;
    __syncthreads();
    for (int o = 128; o; o >>= 1) {
        if (tid < o) { sl[tid] += sl[tid+o]; sa[tid] += sa[tid+o]; }
        __syncthreads();
    }
    if (tid == 0) {
        out[0] = sl[0] / (float)NROWS_L;
        out[1] = sa[0] / (float)NROWS_L * 100.f;
    }
}

// ---------------- copy z and c into d_out (8B-aligned dst) ---------------
__global__ void copyout_kernel(float* __restrict__ out)
{
    long i = (long)blockIdx.x * 256 + threadIdx.x;
    float2* dst = (float2*)(out + 2);
    const long NZ2 = 2097152;
    const long NC2 = 4194304;
    if (i < NZ2) {
        dst[i] = ((const float2*)g_z)[i];
    } else if (i < NZ2 + NC2) {
        dst[i] = ((const float2*)g_c)[i - NZ2];
    }
}

// ---------------- host launcher ------------------------------------------
extern "C" void kernel_launch(void* const* d_in, const int* in_sizes, int n_in,
                              void* d_out, int out_size)
{
    const float* rr  = (const float*)d_in[0];
    const float* w1  = (const float*)d_in[1];
    const float* b1  = (const float*)d_in[2];
    const float* w2  = (const float*)d_in[3];
    const float* b2  = (const float*)d_in[4];
    const float* Wih = (const float*)d_in[5];
    const float* Whh = (const float*)d_in[6];
    const float* bih = (const float*)d_in[7];
    const float* bhh = (const float*)d_in[8];
    const float* Wkw = (const float*)d_in[9];
    const float* Wkb = (const float*)d_in[10];

    float* out = (float*)d_out;

    float *pz, *pc, *ph1, *pgx, *pU, *pw1T, *pw2T, *pWkT;
    cudaGetSymbolAddress((void**)&pz,   g_z);
    cudaGetSymbolAddress((void**)&pc,   g_c);
    cudaGetSymbolAddress((void**)&ph1,  g_h1);
    cudaGetSymbolAddress((void**)&pgx,  g_gx);
    cudaGetSymbolAddress((void**)&pU,   g_U);
    cudaGetSymbolAddress((void**)&pw1T, g_w1T);
    cudaGetSymbolAddress((void**)&pw2T, g_w2T);
    cudaGetSymbolAddress((void**)&pWkT, g_WkT);

    cudaFuncSetAttribute(logits_mma, cudaFuncAttributeMaxDynamicSharedMemorySize, LOG_SMEM);
    cudaFuncSetAttribute(gru4,       cudaFuncAttributeMaxDynamicSharedMemorySize, GRU4_SMEM);
    cudaFuncSetAttribute(mma_gemm,   cudaFuncAttributeMaxDynamicSharedMemorySize, GEMM_SMEM);

    // 0. weight transposes
    prep_transpose<<<1536, 256>>>(w1, w2, Wkw);
    // 1. encoder layer 1 (relu)
    mma_gemm<<<dim3(2, 256, 1), 256, GEMM_SMEM>>>(
        rr, pw1T, b1, ph1, N_BT, 256, 256, 1, 0, 0, 0, 0);
    // 2. encoder layer 2 -> normalized z (mode 2)
    mma_gemm<<<dim3(1, 256, 1), 256, GEMM_SMEM>>>(
        ph1, pw2T, b2, pz, N_BT, 128, 256, 0, 2, 0, 0, 0);
    // 3. gx = z @ W_ih^T + b_ih
    mma_gemm<<<dim3(6, 256, 1), 256, GEMM_SMEM>>>(
        pz, Wih, bih, pgx, N_BT, 768, 128, 0, 0, 0, 0, 0);
    // 4. GRU v4 (register W, permuted h layout)
    gru4<<<128, 256, GRU4_SMEM>>>(Whh, bhh);
    // 5. U[k] = rowscale10(c @ Wk_w[k] + Wk_b[k])  (mode 1)
    mma_gemm<<<dim3(1, 256, 12), 256, GEMM_SMEM>>>(
        pc, pWkT, Wkb, pU, N_BT, 128, 256, 0, 1,
        32768L, 128L, (long)N_BT * 128);
    // 6. fused logits + reductions (tensor-core)
    logits_mma<<<dim3(4, 128, 12), 256, LOG_SMEM>>>();
    // 7. final loss/accuracy
    final_kernel<<<1, 256>>>(out);
    // 8. copy z_seq and c_seq into d_out
    copyout_kernel<<<24576, 256>>>(out);
}